// round 6
// baseline (speedup 1.0000x reference)
#include <cuda_runtime.h>
#include <math.h>

#define NB   8
#define NN   256
#define NH   8
#define NLAT 32
#define SC   0.35355339059327373f

__device__ __align__(16) float g_Q   [NB*NN*64];
__device__ __align__(16) float g_Kt  [NB*64*NN];     // [b][hk][j] pre-scaled
__device__ __align__(16) float g_Vt  [NB*NH*NN*8];   // [b][h][j][d]
__device__ __align__(16) float g_pattn[NB*NN*64];
__device__ __align__(16) float g_KcT [NB*64*NN];     // [b][d][j]
__device__ __align__(16) float g_VcT [NB*64*NN];     // [b][d][j]
__device__ __align__(16) float g_q   [NB*NLAT*64];

__global__ void k_nop() {}

// -------- K0: Q, K*SCALE (transposed), V (head-major). 4 rows/block --------
__global__ void k_qkv(const float* __restrict__ p, const float* __restrict__ wq,
                      const float* __restrict__ wk, const float* __restrict__ wv) {
    int blk = blockIdx.x, t = threadIdx.x;
    int r = t >> 6, col = t & 63;
    int bi = blk*4 + r;
    __shared__ float pr[4][64];
    pr[r][col] = p[bi*64 + col];
    __syncthreads();
    float aq = 0.f, ak = 0.f, av = 0.f;
#pragma unroll 8
    for (int c = 0; c < 64; c++) {
        float pv = pr[r][c];
        aq = fmaf(pv, wq[c*64 + col], aq);
        ak = fmaf(pv, wk[c*64 + col], ak);
        av = fmaf(pv, wv[c*64 + col], av);
    }
    int b = bi >> 8, j = bi & 255;
    g_Q[bi*64 + col] = aq;
    g_Kt[(b*64 + col)*256 + j] = ak * SC;
    g_Vt[(((b*8 + (col >> 3))*256) + j)*8 + (col & 7)] = av;
}

// -------- K1: per-(b,i) GEMM, c-packed f32x2, fused softmax/kRW/PV --------
// smem: Wp[32cp][64hk] ULL (16KB) | e_s[128][66] (33.8KB) | qrow[64]
#define EDGE_SMEM (16384 + 128*66*4 + 256)
__global__ void __launch_bounds__(256, 2) k_edge(const float* __restrict__ e,
                                                 const float* __restrict__ we,
                                                 const float* __restrict__ mask,
                                                 const float* __restrict__ kRW) {
    extern __shared__ float sm[];
    float* Wpf  = sm;                    // 4096 floats = 2048 ULL pairs
    float* e_s  = sm + 4096;             // [128][66]
    float* qrow = sm + 4096 + 128*66;
    int tid = threadIdx.x, bi = blockIdx.x, b = bi >> 8, i = bi & 255;
    if (tid < 64) qrow[tid] = g_Q[bi*64 + tid];
    __syncthreads();
    // Wp[cp*64+hk] = {we[2cp][hk]*q[hk], we[2cp+1][hk]*q[hk]}
    for (int idx = tid; idx < 2048; idx += 256) {
        int cp = idx >> 6, hk = idx & 63;
        float qv = qrow[hk];
        float2 wp = {we[(2*cp)*64 + hk]*qv, we[(2*cp + 1)*64 + hk]*qv};
        *(float2*)&Wpf[idx*2] = wp;
    }

    int tj = tid & 31, th = tid >> 5;
    const float* Ktb = g_Kt + (b*64 + th*8)*256;
    const float4* eg = ((const float4*)e) + (size_t)bi*4096;
    const unsigned long long* Wp = (const unsigned long long*)Wpf;
    float s[8];

#pragma unroll
    for (int ch = 0; ch < 2; ch++) {
        __syncthreads();
        for (int v = tid; v < 2048; v += 256) {
            float4 x = eg[ch*2048 + v];
            float* d = &e_s[(v >> 4)*66 + (v & 15)*4];
            d[0] = x.x; d[1] = x.y; d[2] = x.z; d[3] = x.w;
        }
        __syncthreads();
        unsigned long long acc[32];   // [jj][hk] lo=even-c, hi=odd-c partials
#pragma unroll
        for (int a = 0; a < 32; a++) acc[a] = 0ULL;
#pragma unroll 2
        for (int cp = 0; cp < 32; cp++) {
            unsigned long long e2[4];
#pragma unroll
            for (int jj = 0; jj < 4; jj++)
                e2[jj] = *(const unsigned long long*)&e_s[(tj + jj*32)*66 + 2*cp];
            const unsigned long long* wr = Wp + cp*64 + th*8;
#pragma unroll
            for (int k = 0; k < 8; k++) {
                unsigned long long wv = wr[k];
                asm("fma.rn.f32x2 %0,%1,%2,%0;" : "+l"(acc[0*8+k]) : "l"(e2[0]), "l"(wv));
                asm("fma.rn.f32x2 %0,%1,%2,%0;" : "+l"(acc[1*8+k]) : "l"(e2[1]), "l"(wv));
                asm("fma.rn.f32x2 %0,%1,%2,%0;" : "+l"(acc[2*8+k]) : "l"(e2[2]), "l"(wv));
                asm("fma.rn.f32x2 %0,%1,%2,%0;" : "+l"(acc[3*8+k]) : "l"(e2[3]), "l"(wv));
            }
        }
#pragma unroll
        for (int jj = 0; jj < 4; jj++) {
            int j = ch*128 + tj + jj*32;
            float ss = 0.f;
#pragma unroll
            for (int k = 0; k < 8; k++) {
                unsigned long long a = acc[jj*8 + k];
                float lo = __uint_as_float((unsigned int)a);
                float hi = __uint_as_float((unsigned int)(a >> 32));
                ss = fmaf(lo + hi, Ktb[k*256 + j], ss);
            }
            s[ch*4 + jj] = ss;
        }
    }

    // row max (ratio is max-shift invariant; local max validated)
    float m = s[0];
#pragma unroll
    for (int k = 1; k < 8; k++) m = fmaxf(m, s[k]);
#pragma unroll
    for (int off = 16; off; off >>= 1)
        m = fmaxf(m, __shfl_xor_sync(0xffffffffu, m, off));

    float mi = mask[b*256 + i];
    const float* krow = kRW + ((size_t)b*256 + i)*256;
    const float* Vb = g_Vt + ((size_t)(b*8 + th)*256)*8;
    float av[9] = {0,0,0,0,0,0,0,0,0};
#pragma unroll
    for (int k = 0; k < 8; k++) {
        int j = (k >> 2)*128 + tj + (k & 3)*32;
        float wgt = __expf(s[k] - m) * mi * mask[b*256 + j] * krow[j];
        av[0] += wgt;
        const float4* V4 = (const float4*)(Vb + j*8);
        float4 va = V4[0], vb = V4[1];
        av[1] = fmaf(wgt, va.x, av[1]); av[2] = fmaf(wgt, va.y, av[2]);
        av[3] = fmaf(wgt, va.z, av[3]); av[4] = fmaf(wgt, va.w, av[4]);
        av[5] = fmaf(wgt, vb.x, av[5]); av[6] = fmaf(wgt, vb.y, av[6]);
        av[7] = fmaf(wgt, vb.z, av[7]); av[8] = fmaf(wgt, vb.w, av[8]);
    }
#pragma unroll
    for (int kk = 0; kk < 9; kk++)
#pragma unroll
        for (int off = 16; off; off >>= 1)
            av[kk] += __shfl_xor_sync(0xffffffffu, av[kk], off);
    if (tj == 0) {
        float inv = 1.f / fmaxf(av[0], 1e-6f);
        float4 o1 = {av[1]*inv, av[2]*inv, av[3]*inv, av[4]*inv};
        float4 o2 = {av[5]*inv, av[6]*inv, av[7]*inv, av[8]*inv};
        float4* dst = (float4*)(g_pattn + ((size_t)(b*256 + i))*64 + th*8);
        dst[0] = o1; dst[1] = o2;
    }
}

// -------- K2: h_c + tanh proj fused with transposed Kc/Vc projection --------
__global__ void k_hckv(const float* __restrict__ hh, const float* __restrict__ p,
                       const float* __restrict__ wo, const float* __restrict__ wkv) {
    int blk = blockIdx.x, t = threadIdx.x;
    int bi0 = blk*8, b = bi0 >> 8;
    __shared__ float pa[8][64], hcs[8][64];
    {
        int r = t >> 6, col = t & 63;
        pa[r][col]     = g_pattn[(bi0 + r)*64 + col];
        pa[r + 4][col] = g_pattn[(bi0 + r + 4)*64 + col];
    }
    __syncthreads();
    {
        int rp = t >> 6, col = t & 63;
        float a0 = 0.f, a1 = 0.f;
#pragma unroll 8
        for (int c = 0; c < 64; c++) {
            float wv = wo[c*64 + col];
            a0 = fmaf(pa[rp][c], wv, a0);
            a1 = fmaf(pa[rp + 4][c], wv, a1);
        }
        int bi = bi0 + rp;
        hcs[rp][col]     = hh[bi*64 + col] + p[bi*64 + col] + tanhf(a0);
        hcs[rp + 4][col] = hh[(bi + 4)*64 + col] + p[(bi + 4)*64 + col] + tanhf(a1);
    }
    __syncthreads();
    {
        int o = t & 127, rq = t >> 7;
        float a[4] = {0, 0, 0, 0};
#pragma unroll 8
        for (int c = 0; c < 64; c++) {
            float wv = wkv[c*128 + o];
#pragma unroll
            for (int k = 0; k < 4; k++) a[k] = fmaf(hcs[rq + 2*k][c], wv, a[k]);
        }
#pragma unroll
        for (int k = 0; k < 4; k++) {
            int j = (bi0 & 255) + rq + 2*k;
            if (o < 64) g_KcT[(b*64 + o)*256 + j] = a[k];
            else        g_VcT[(b*64 + (o - 64))*256 + j] = a[k];
        }
    }
}

// -------- K3: perceiver cross-attention, coalesced via KcT/VcT --------
__global__ void k_cross(const float* __restrict__ queries, const float* __restrict__ mask,
                        const float* __restrict__ wq, const float* __restrict__ wo,
                        const float* __restrict__ bo) {
    int blk = blockIdx.x, b = blk >> 5, t = threadIdx.x;
    __shared__ float q2[64];
    __shared__ float sq[64];
    __shared__ float att[64];
    __shared__ float simb[8*256];
    if (t < 64) sq[t] = queries[blk*64 + t];
    __syncthreads();
    if (t < 64) {
        float a = 0.f;
#pragma unroll 8
        for (int c = 0; c < 64; c++) a = fmaf(sq[c], wq[c*64 + t], a);
        q2[t] = a;
    }
    __syncthreads();
    {
        int j = t;
        bool mk = mask[b*256 + j] > 0.5f;
        float sh[8] = {0,0,0,0,0,0,0,0};
        const float* KT = g_KcT + (size_t)b*64*256 + j;
#pragma unroll 8
        for (int d = 0; d < 64; d++)
            sh[d >> 3] = fmaf(q2[d], KT[d*256], sh[d >> 3]);
#pragma unroll
        for (int h = 0; h < 8; h++) {
            float s = sh[h] * SC;
            if (!mk) s = -3.402823466e38f;
            simb[h*256 + j] = fminf(5.f, fmaxf(-5.f, s));
        }
    }
    __syncthreads();
    int h = t >> 5, lane = t & 31;
    {
        float sum = 0.f, o[8] = {0,0,0,0,0,0,0,0};
        const float* VT = g_VcT + (size_t)b*64*256 + h*8*256;
        for (int j = lane; j < 256; j += 32) {
            float ev = __expf(simb[h*256 + j]);
            sum += ev;
#pragma unroll
            for (int d = 0; d < 8; d++) o[d] = fmaf(ev, VT[d*256 + j], o[d]);
        }
#pragma unroll
        for (int off = 16; off; off >>= 1) {
            sum += __shfl_xor_sync(0xffffffffu, sum, off);
#pragma unroll
            for (int d = 0; d < 8; d++) o[d] += __shfl_xor_sync(0xffffffffu, o[d], off);
        }
        if (lane == 0) {
            float inv = 1.f / sum;
#pragma unroll
            for (int d = 0; d < 8; d++) att[h*8 + d] = o[d]*inv;
        }
    }
    __syncthreads();
    if (t < 64) {
        float a = bo[t];
#pragma unroll 8
        for (int c = 0; c < 64; c++) a = fmaf(att[c], wo[c*64 + t], a);
        g_q[blk*64 + t] = sq[t] + a;
    }
}

// -------- K4: 2 latent self-attn layers + O_queries + LN + FFN + LN, per-batch --------
#define SF_SMEM ((2048*6 + 4096 + 64) * 4)
__global__ void __launch_bounds__(256) k_selffinal(
        const float* __restrict__ sa_wq, const float* __restrict__ sa_wkv,
        const float* __restrict__ sa_wo, const float* __restrict__ sa_bo,
        const float* __restrict__ oq,  const float* __restrict__ g1,
        const float* __restrict__ b1,  const float* __restrict__ w1,
        const float* __restrict__ w2,  const float* __restrict__ g2,
        const float* __restrict__ b2,  float* __restrict__ out) {
    extern __shared__ float sm[];
    float* qs = sm;
    float* q2 = sm + 2048;
    float* Ks = sm + 4096;
    float* Vs = sm + 6144;
    float* att= sm + 8192;
    float* ys = sm + 10240;
    float* f1 = sm + 12288;
    float* mu = sm + 16384;
    float* rv = sm + 16416;
    int b = blockIdx.x, t = threadIdx.x;
    int o = t & 63, l0 = t >> 6;
    int o2 = t & 127, l1 = t >> 7;
#pragma unroll
    for (int k = 0; k < 8; k++) qs[t + 256*k] = g_q[b*2048 + t + 256*k];

    for (int layer = 0; layer < 2; layer++) {
        const float* wq  = sa_wq  + layer*4096;
        const float* wkv = sa_wkv + layer*8192;
        const float* wo  = sa_wo  + layer*4096;
        const float* bo  = sa_bo  + layer*64;
        __syncthreads();
        {
            float a[8] = {0,0,0,0,0,0,0,0};
#pragma unroll 4
            for (int c = 0; c < 64; c++) {
                float w = wq[c*64 + o];
#pragma unroll
                for (int k = 0; k < 8; k++) a[k] = fmaf(qs[(l0 + 4*k)*64 + c], w, a[k]);
            }
#pragma unroll
            for (int k = 0; k < 8; k++) q2[(l0 + 4*k)*64 + o] = a[k];
        }
        {
            float a[16];
#pragma unroll
            for (int k = 0; k < 16; k++) a[k] = 0.f;
#pragma unroll 4
            for (int c = 0; c < 64; c++) {
                float w = wkv[c*128 + o2];
#pragma unroll
                for (int k = 0; k < 16; k++) a[k] = fmaf(qs[(l1 + 2*k)*64 + c], w, a[k]);
            }
#pragma unroll
            for (int k = 0; k < 16; k++) {
                int l = l1 + 2*k;
                if (o2 < 64) Ks[l*64 + o2] = a[k]; else Vs[l*64 + (o2 - 64)] = a[k];
            }
        }
        __syncthreads();
        {
            int h = t >> 5, i = t & 31;
            float qh[8];
#pragma unroll
            for (int d = 0; d < 8; d++) qh[d] = q2[i*64 + h*8 + d];
            float sum = 0.f, ov[8] = {0,0,0,0,0,0,0,0};
#pragma unroll 4
            for (int j = 0; j < 32; j++) {
                float s = 0.f;
#pragma unroll
                for (int d = 0; d < 8; d++) s = fmaf(qh[d], Ks[j*64 + h*8 + d], s);
                s = fminf(5.f, fmaxf(-5.f, s*SC));
                float w = __expf(s);
                sum += w;
#pragma unroll
                for (int d = 0; d < 8; d++) ov[d] = fmaf(w, Vs[j*64 + h*8 + d], ov[d]);
            }
            float inv = 1.f / sum;
#pragma unroll
            for (int d = 0; d < 8; d++) att[i*64 + h*8 + d] = ov[d]*inv;
        }
        __syncthreads();
        {
            float a[8] = {0,0,0,0,0,0,0,0};
#pragma unroll 4
            for (int c = 0; c < 64; c++) {
                float w = wo[c*64 + o];
#pragma unroll
                for (int k = 0; k < 8; k++) a[k] = fmaf(att[(l0 + 4*k)*64 + c], w, a[k]);
            }
            float bv = bo[o];
#pragma unroll
            for (int k = 0; k < 8; k++) qs[(l0 + 4*k)*64 + o] += a[k] + bv;
        }
    }
    __syncthreads();
    {
        float a[8] = {0,0,0,0,0,0,0,0};
#pragma unroll 4
        for (int c = 0; c < 64; c++) {
            float w = oq[c*64 + o];
#pragma unroll
            for (int k = 0; k < 8; k++) a[k] = fmaf(qs[(l0 + 4*k)*64 + c], w, a[k]);
        }
#pragma unroll
        for (int k = 0; k < 8; k++) q2[(l0 + 4*k)*64 + o] = a[k];
    }
    __syncthreads();
    if (t < 32) {
        float su = 0.f, sq2 = 0.f;
#pragma unroll 8
        for (int c = 0; c < 64; c++) { float v = q2[t*64 + c]; su += v; sq2 += v*v; }
        float mm = su/64.f;
        mu[t] = mm; rv[t] = rsqrtf(sq2/64.f - mm*mm + 1e-5f);
    }
    __syncthreads();
#pragma unroll
    for (int k = 0; k < 8; k++) {
        int idx = t + 256*k;
        int l = idx >> 6, c = idx & 63;
        ys[idx] = (q2[idx] - mu[l])*rv[l]*g1[c] + b1[c];
    }
    __syncthreads();
    {
        float a[16];
#pragma unroll
        for (int k = 0; k < 16; k++) a[k] = 0.f;
#pragma unroll 4
        for (int c = 0; c < 64; c++) {
            float w = w1[c*128 + o2];
#pragma unroll
            for (int k = 0; k < 16; k++) a[k] = fmaf(ys[(l1 + 2*k)*64 + c], w, a[k]);
        }
#pragma unroll
        for (int k = 0; k < 16; k++) f1[(l1 + 2*k)*128 + o2] = fmaxf(a[k], 0.f);
    }
    __syncthreads();
    {
        float a[8] = {0,0,0,0,0,0,0,0};
#pragma unroll 4
        for (int c = 0; c < 128; c++) {
            float w = w2[c*64 + o];
#pragma unroll
            for (int k = 0; k < 8; k++) a[k] = fmaf(f1[(l0 + 4*k)*128 + c], w, a[k]);
        }
#pragma unroll
        for (int k = 0; k < 8; k++) {
            int l = l0 + 4*k;
            q2[l*64 + o] = ys[l*64 + o] + a[k];
        }
    }
    __syncthreads();
    if (t < 32) {
        float su = 0.f, sq2 = 0.f;
#pragma unroll 8
        for (int c = 0; c < 64; c++) { float v = q2[t*64 + c]; su += v; sq2 += v*v; }
        float mm = su/64.f;
        mu[t] = mm; rv[t] = rsqrtf(sq2/64.f - mm*mm + 1e-5f);
    }
    __syncthreads();
#pragma unroll
    for (int k = 0; k < 8; k++) {
        int idx = t + 256*k;
        int l = idx >> 6, c = idx & 63;
        out[b*2048 + idx] = (q2[idx] - mu[l])*rv[l]*g2[c] + b2[c];
    }
}

extern "C" void kernel_launch(void* const* d_in, const int* in_sizes, int n_in,
                              void* d_out, int out_size) {
    const float* h_    = (const float*)d_in[0];
    const float* p     = (const float*)d_in[1];
    const float* e     = (const float*)d_in[2];
    const float* kRW   = (const float*)d_in[3];
    const float* qrs   = (const float*)d_in[4];
    const float* mask  = (const float*)d_in[5];
    const float* wq_p  = (const float*)d_in[6];
    const float* wk_p  = (const float*)d_in[7];
    const float* we_p  = (const float*)d_in[8];
    const float* wv_p  = (const float*)d_in[9];
    const float* wo_p  = (const float*)d_in[10];
    const float* cq_wq = (const float*)d_in[11];
    const float* cq_wkv= (const float*)d_in[12];
    const float* cq_wo = (const float*)d_in[13];
    const float* cq_bo = (const float*)d_in[14];
    const float* sa_wq = (const float*)d_in[15];
    const float* sa_wkv= (const float*)d_in[16];
    const float* sa_wo = (const float*)d_in[17];
    const float* sa_bo = (const float*)d_in[18];
    const float* oq_w  = (const float*)d_in[19];
    const float* ln1g  = (const float*)d_in[20];
    const float* ln1b  = (const float*)d_in[21];
    const float* fw1   = (const float*)d_in[22];
    const float* fw2   = (const float*)d_in[23];
    const float* ln2g  = (const float*)d_in[24];
    const float* ln2b  = (const float*)d_in[25];
    float* out = (float*)d_out;

    static int configured = 0;
    if (!configured) {
        cudaFuncSetAttribute(k_edge, cudaFuncAttributeMaxDynamicSharedMemorySize, EDGE_SMEM);
        cudaFuncSetAttribute(k_selffinal, cudaFuncAttributeMaxDynamicSharedMemorySize, SF_SMEM);
        configured = 1;
    }

    k_qkv      <<<NB*NN/4, 256>>>(p, wq_p, wk_p, wv_p);   // launch 1
    k_nop      <<<1, 32>>>();                              // launch 2
    k_nop      <<<1, 32>>>();                              // launch 3
    k_edge     <<<NB*NN, 256, EDGE_SMEM>>>(e, we_p, mask, kRW);   // launch 4 -> profiled
    k_hckv     <<<NB*NN/8, 256>>>(h_, p, wo_p, cq_wkv);
    k_cross    <<<NB*NLAT, 256>>>(qrs, mask, cq_wq, cq_wo, cq_bo);
    k_selffinal<<<NB, 256, SF_SMEM>>>(sa_wq, sa_wkv, sa_wo, sa_bo,
                                      oq_w, ln1g, ln1b, fw1, fw2, ln2g, ln2b, out);
}

// round 7
// speedup vs baseline: 1.2925x; 1.2925x over previous
#include <cuda_runtime.h>
#include <math.h>

#define NB   8
#define NN   256
#define NH   8
#define NLAT 32
#define SC   0.35355339059327373f

__device__ __align__(16) float g_Q   [NB*NN*64];
__device__ __align__(16) float g_Kt  [NB*64*NN];     // [b][hk][j] pre-scaled
__device__ __align__(16) float g_Vt  [NB*NH*NN*8];   // [b][h][j][d]
__device__ __align__(16) float g_pattn[NB*NN*64];
__device__ __align__(16) float g_KcT [NB*64*NN];     // [b][d][j]
__device__ __align__(16) float g_VcT [NB*64*NN];     // [b][d][j]
__device__ __align__(16) float g_q   [NB*NLAT*64];
__device__ __align__(16) float g_q2  [NB*NLAT*64];
__device__ __align__(16) float g_Kl  [NB*NLAT*64];
__device__ __align__(16) float g_Vl  [NB*NLAT*64];

// -------- K0: Q, K*SCALE (transposed), V (head-major). 4 rows/block --------
__global__ void k_qkv(const float* __restrict__ p, const float* __restrict__ wq,
                      const float* __restrict__ wk, const float* __restrict__ wv) {
    int blk = blockIdx.x, t = threadIdx.x;
    int r = t >> 6, col = t & 63;
    int bi = blk*4 + r;
    __shared__ float pr[4][64];
    pr[r][col] = p[bi*64 + col];
    __syncthreads();
    float aq = 0.f, ak = 0.f, av = 0.f;
#pragma unroll 8
    for (int c = 0; c < 64; c++) {
        float pv = pr[r][c];
        aq = fmaf(pv, wq[c*64 + col], aq);
        ak = fmaf(pv, wk[c*64 + col], ak);
        av = fmaf(pv, wv[c*64 + col], av);
    }
    int b = bi >> 8, j = bi & 255;
    g_Q[bi*64 + col] = aq;
    g_Kt[(b*64 + col)*256 + j] = ak * SC;
    g_Vt[(((b*8 + (col >> 3))*256) + j)*8 + (col & 7)] = av;
}

// -------- K1: per-(b,i) GEMM (2 chunks of 128 j) + fused softmax/kRW/PV --------
// smem: W_s[4096] | e_s[128*65] | qrow[64] = 12480 floats = 49920 B dynamic
#define EDGE_SMEM ((4096 + 128*65 + 64)*4)
__global__ void __launch_bounds__(256, 3) k_edge(const float* __restrict__ e,
                                                 const float* __restrict__ we,
                                                 const float* __restrict__ mask,
                                                 const float* __restrict__ kRW) {
    extern __shared__ float sm[];
    float* W_s  = sm;
    float* e_s  = sm + 4096;
    float* qrow = sm + 4096 + 128*65;
    int tid = threadIdx.x, bi = blockIdx.x, b = bi >> 8, i = bi & 255;
    if (tid < 64) qrow[tid] = g_Q[bi*64 + tid];
    __syncthreads();
    for (int idx = tid; idx < 4096; idx += 256) W_s[idx] = we[idx] * qrow[idx & 63];

    int tj = tid & 31, th = tid >> 5;
    const float* Ktb = g_Kt + (b*64 + th*8)*256;
    const float4* eg = ((const float4*)e) + (size_t)bi*4096;
    float s[8];

#pragma unroll
    for (int ch = 0; ch < 2; ch++) {
        __syncthreads();
        for (int v = tid; v < 2048; v += 256) {
            float4 x = eg[ch*2048 + v];
            float* d = &e_s[(v >> 4)*65 + (v & 15)*4];
            d[0] = x.x; d[1] = x.y; d[2] = x.z; d[3] = x.w;
        }
        __syncthreads();
        unsigned long long acc[16];
#pragma unroll
        for (int a = 0; a < 16; a++) acc[a] = 0ULL;
#pragma unroll 2
        for (int c = 0; c < 64; c++) {
            const float* wrow = W_s + c*64 + th*8;
            unsigned long long w0 = *(const unsigned long long*)(wrow);
            unsigned long long w1 = *(const unsigned long long*)(wrow + 2);
            unsigned long long w2 = *(const unsigned long long*)(wrow + 4);
            unsigned long long w3 = *(const unsigned long long*)(wrow + 6);
#pragma unroll
            for (int jj = 0; jj < 4; jj++) {
                float ev = e_s[(tj + jj*32)*65 + c];
                unsigned long long dd;
                asm("mov.b64 %0,{%1,%1};" : "=l"(dd) : "r"(__float_as_uint(ev)));
                asm("fma.rn.f32x2 %0,%1,%2,%0;" : "+l"(acc[jj*4+0]) : "l"(dd), "l"(w0));
                asm("fma.rn.f32x2 %0,%1,%2,%0;" : "+l"(acc[jj*4+1]) : "l"(dd), "l"(w1));
                asm("fma.rn.f32x2 %0,%1,%2,%0;" : "+l"(acc[jj*4+2]) : "l"(dd), "l"(w2));
                asm("fma.rn.f32x2 %0,%1,%2,%0;" : "+l"(acc[jj*4+3]) : "l"(dd), "l"(w3));
            }
        }
#pragma unroll
        for (int jj = 0; jj < 4; jj++) {
            int j = ch*128 + tj + jj*32;
            float ss = 0.f;
#pragma unroll
            for (int pp = 0; pp < 4; pp++) {
                unsigned long long a = acc[jj*4 + pp];
                float lo = __uint_as_float((unsigned int)a);
                float hi = __uint_as_float((unsigned int)(a >> 32));
                ss = fmaf(lo, Ktb[(2*pp)*256 + j], ss);
                ss = fmaf(hi, Ktb[(2*pp + 1)*256 + j], ss);
            }
            s[ch*4 + jj] = ss;
        }
    }

    // row max (ratio is max-shift invariant; local max validated rel_err 1.3e-7)
    float m = s[0];
#pragma unroll
    for (int k = 1; k < 8; k++) m = fmaxf(m, s[k]);
#pragma unroll
    for (int off = 16; off; off >>= 1)
        m = fmaxf(m, __shfl_xor_sync(0xffffffffu, m, off));

    float mi = mask[b*256 + i];
    const float* krow = kRW + ((size_t)b*256 + i)*256;
    const float* Vb = g_Vt + ((size_t)(b*8 + th)*256)*8;
    float av[9] = {0,0,0,0,0,0,0,0,0};
#pragma unroll
    for (int k = 0; k < 8; k++) {
        int j = (k >> 2)*128 + tj + (k & 3)*32;
        float wgt = __expf(s[k] - m) * mi * mask[b*256 + j] * krow[j];
        av[0] += wgt;
        const float4* V4 = (const float4*)(Vb + j*8);
        float4 va = V4[0], vb = V4[1];
        av[1] = fmaf(wgt, va.x, av[1]); av[2] = fmaf(wgt, va.y, av[2]);
        av[3] = fmaf(wgt, va.z, av[3]); av[4] = fmaf(wgt, va.w, av[4]);
        av[5] = fmaf(wgt, vb.x, av[5]); av[6] = fmaf(wgt, vb.y, av[6]);
        av[7] = fmaf(wgt, vb.z, av[7]); av[8] = fmaf(wgt, vb.w, av[8]);
    }
#pragma unroll
    for (int kk = 0; kk < 9; kk++)
#pragma unroll
        for (int off = 16; off; off >>= 1)
            av[kk] += __shfl_xor_sync(0xffffffffu, av[kk], off);
    if (tj == 0) {
        float inv = 1.f / fmaxf(av[0], 1e-6f);
        float4 o1 = {av[1]*inv, av[2]*inv, av[3]*inv, av[4]*inv};
        float4 o2 = {av[5]*inv, av[6]*inv, av[7]*inv, av[8]*inv};
        float4* dst = (float4*)(g_pattn + ((size_t)(b*256 + i))*64 + th*8);
        dst[0] = o1; dst[1] = o2;
    }
}

// -------- K2: h_c + tanh proj fused with transposed Kc/Vc projection --------
__global__ void k_hckv(const float* __restrict__ hh, const float* __restrict__ p,
                       const float* __restrict__ wo, const float* __restrict__ wkv) {
    int blk = blockIdx.x, t = threadIdx.x;
    int bi0 = blk*8, b = bi0 >> 8;
    __shared__ float pa[8][64], hcs[8][64];
    {
        int r = t >> 6, col = t & 63;
        pa[r][col]     = g_pattn[(bi0 + r)*64 + col];
        pa[r + 4][col] = g_pattn[(bi0 + r + 4)*64 + col];
    }
    __syncthreads();
    {
        int rp = t >> 6, col = t & 63;
        float a0 = 0.f, a1 = 0.f;
#pragma unroll 8
        for (int c = 0; c < 64; c++) {
            float wv = wo[c*64 + col];
            a0 = fmaf(pa[rp][c], wv, a0);
            a1 = fmaf(pa[rp + 4][c], wv, a1);
        }
        int bi = bi0 + rp;
        hcs[rp][col]     = hh[bi*64 + col] + p[bi*64 + col] + tanhf(a0);
        hcs[rp + 4][col] = hh[(bi + 4)*64 + col] + p[(bi + 4)*64 + col] + tanhf(a1);
    }
    __syncthreads();
    {
        int o = t & 127, rq = t >> 7;
        float a[4] = {0, 0, 0, 0};
#pragma unroll 8
        for (int c = 0; c < 64; c++) {
            float wv = wkv[c*128 + o];
#pragma unroll
            for (int k = 0; k < 4; k++) a[k] = fmaf(hcs[rq + 2*k][c], wv, a[k]);
        }
#pragma unroll
        for (int k = 0; k < 4; k++) {
            int j = (bi0 & 255) + rq + 2*k;
            if (o < 64) g_KcT[(b*64 + o)*256 + j] = a[k];
            else        g_VcT[(b*64 + (o - 64))*256 + j] = a[k];
        }
    }
}

// -------- K3: perceiver cross-attention, coalesced via KcT/VcT --------
__global__ void k_cross(const float* __restrict__ queries, const float* __restrict__ mask,
                        const float* __restrict__ wq, const float* __restrict__ wo,
                        const float* __restrict__ bo) {
    int blk = blockIdx.x, b = blk >> 5, t = threadIdx.x;
    __shared__ float q2[64];
    __shared__ float sq[64];
    __shared__ float att[64];
    __shared__ float simb[8*256];
    if (t < 64) sq[t] = queries[blk*64 + t];
    __syncthreads();
    if (t < 64) {
        float a = 0.f;
#pragma unroll 8
        for (int c = 0; c < 64; c++) a = fmaf(sq[c], wq[c*64 + t], a);
        q2[t] = a;
    }
    __syncthreads();
    {
        int j = t;
        bool mk = mask[b*256 + j] > 0.5f;
        float sh[8] = {0,0,0,0,0,0,0,0};
        const float* KT = g_KcT + (size_t)b*64*256 + j;
#pragma unroll 8
        for (int d = 0; d < 64; d++)
            sh[d >> 3] = fmaf(q2[d], KT[d*256], sh[d >> 3]);
#pragma unroll
        for (int h = 0; h < 8; h++) {
            float s = sh[h] * SC;
            if (!mk) s = -3.402823466e38f;
            simb[h*256 + j] = fminf(5.f, fmaxf(-5.f, s));
        }
    }
    __syncthreads();
    int h = t >> 5, lane = t & 31;
    {
        float sum = 0.f, o[8] = {0,0,0,0,0,0,0,0};
        const float* VT = g_VcT + (size_t)b*64*256 + h*8*256;
        for (int j = lane; j < 256; j += 32) {
            float ev = __expf(simb[h*256 + j]);
            sum += ev;
#pragma unroll
            for (int d = 0; d < 8; d++) o[d] = fmaf(ev, VT[d*256 + j], o[d]);
        }
#pragma unroll
        for (int off = 16; off; off >>= 1) {
            sum += __shfl_xor_sync(0xffffffffu, sum, off);
#pragma unroll
            for (int d = 0; d < 8; d++) o[d] += __shfl_xor_sync(0xffffffffu, o[d], off);
        }
        if (lane == 0) {
            float inv = 1.f / sum;
#pragma unroll
            for (int d = 0; d < 8; d++) att[h*8 + d] = o[d]*inv;
        }
    }
    __syncthreads();
    if (t < 64) {
        float a = bo[t];
#pragma unroll 8
        for (int c = 0; c < 64; c++) a = fmaf(att[c], wo[c*64 + t], a);
        g_q[blk*64 + t] = sq[t] + a;
    }
}

// -------- K4a: latent self-attn projections (256 blocks) --------
__global__ void k_selfqkv(const float* __restrict__ wq, const float* __restrict__ wkv) {
    int blk = blockIdx.x, t = threadIdx.x;
    __shared__ float qr[64];
    if (t < 64) qr[t] = g_q[blk*64 + t];
    __syncthreads();
    if (t < 64) {
        float a = 0.f;
#pragma unroll 8
        for (int c = 0; c < 64; c++) a = fmaf(qr[c], wq[c*64 + t], a);
        g_q2[blk*64 + t] = a;
    } else {
        int o = t - 64;
        float a = 0.f;
#pragma unroll 8
        for (int c = 0; c < 64; c++) a = fmaf(qr[c], wkv[c*128 + o], a);
        if (o < 64) g_Kl[blk*64 + o] = a; else g_Vl[blk*64 + (o - 64)] = a;
    }
}

// -------- K4b: latent self-attn core + proj + residual (256 blocks) --------
__global__ void k_self(const float* __restrict__ wo, const float* __restrict__ bo) {
    int blk = blockIdx.x, b = blk >> 5, t = threadIdx.x;
    __shared__ float Ks[NLAT*64], Vs[NLAT*64], q2r[64], att[64];
    for (int idx = t; idx < NLAT*64; idx += 256) {
        Ks[idx] = g_Kl[b*NLAT*64 + idx];
        Vs[idx] = g_Vl[b*NLAT*64 + idx];
    }
    if (t < 64) q2r[t] = g_q2[blk*64 + t];
    __syncthreads();
    int h = t >> 5, j = t & 31;
    float s = 0.f;
#pragma unroll
    for (int k = 0; k < 8; k++) s = fmaf(q2r[h*8 + k], Ks[j*64 + h*8 + k], s);
    s *= SC;
    s = fminf(5.f, fmaxf(-5.f, s));
    float ev = __expf(s);
    float sum = ev;
#pragma unroll
    for (int off = 16; off; off >>= 1)
        sum += __shfl_xor_sync(0xffffffffu, sum, off);
    float o[8];
#pragma unroll
    for (int d = 0; d < 8; d++) o[d] = ev * Vs[j*64 + h*8 + d];
#pragma unroll
    for (int off = 16; off; off >>= 1)
#pragma unroll
        for (int d = 0; d < 8; d++) o[d] += __shfl_xor_sync(0xffffffffu, o[d], off);
    if (j == 0) {
        float inv = 1.f / sum;
#pragma unroll
        for (int d = 0; d < 8; d++) att[h*8 + d] = o[d]*inv;
    }
    __syncthreads();
    if (t < 64) {
        float a = bo[t];
#pragma unroll 8
        for (int c = 0; c < 64; c++) a = fmaf(att[c], wo[c*64 + t], a);
        g_q[blk*64 + t] += a;
    }
}

// -------- K5: oq_w @ + LN1 + FFN + LN2 -> out (256 blocks) --------
__global__ void k_final(const float* __restrict__ oq, const float* __restrict__ g1,
                        const float* __restrict__ b1, const float* __restrict__ w1,
                        const float* __restrict__ w2, const float* __restrict__ g2,
                        const float* __restrict__ b2, float* __restrict__ out) {
    int blk = blockIdx.x, t = threadIdx.x;
    __shared__ float qr[64], x[64], y[64], f1[128], z[64], mv[2];
    if (t < 64) qr[t] = g_q[blk*64 + t];
    __syncthreads();
    if (t < 64) {
        float a = 0.f;
#pragma unroll 8
        for (int c = 0; c < 64; c++) a = fmaf(qr[c], oq[c*64 + t], a);
        x[t] = a;
    }
    __syncthreads();
    if (t < 32) {
        float a = x[t], bb = x[t + 32];
        float su = a + bb, sq = a*a + bb*bb;
#pragma unroll
        for (int off = 16; off; off >>= 1) {
            su += __shfl_xor_sync(0xffffffffu, su, off);
            sq += __shfl_xor_sync(0xffffffffu, sq, off);
        }
        if (t == 0) { mv[0] = su/64.f; mv[1] = sq/64.f - (su/64.f)*(su/64.f); }
    }
    __syncthreads();
    if (t < 64)
        y[t] = (x[t] - mv[0])*rsqrtf(mv[1] + 1e-5f)*g1[t] + b1[t];
    __syncthreads();
    {
        float a = 0.f;
#pragma unroll 8
        for (int c = 0; c < 64; c++) a = fmaf(y[c], w1[c*128 + t], a);
        f1[t] = fmaxf(a, 0.f);
    }
    __syncthreads();
    if (t < 64) {
        float a = 0.f;
#pragma unroll 8
        for (int c = 0; c < 128; c++) a = fmaf(f1[c], w2[c*64 + t], a);
        z[t] = y[t] + a;
    }
    __syncthreads();
    if (t < 32) {
        float a = z[t], bb = z[t + 32];
        float su = a + bb, sq = a*a + bb*bb;
#pragma unroll
        for (int off = 16; off; off >>= 1) {
            su += __shfl_xor_sync(0xffffffffu, su, off);
            sq += __shfl_xor_sync(0xffffffffu, sq, off);
        }
        if (t == 0) { mv[0] = su/64.f; mv[1] = sq/64.f - (su/64.f)*(su/64.f); }
    }
    __syncthreads();
    if (t < 64)
        out[blk*64 + t] = (z[t] - mv[0])*rsqrtf(mv[1] + 1e-5f)*g2[t] + b2[t];
}

extern "C" void kernel_launch(void* const* d_in, const int* in_sizes, int n_in,
                              void* d_out, int out_size) {
    const float* h_    = (const float*)d_in[0];
    const float* p     = (const float*)d_in[1];
    const float* e     = (const float*)d_in[2];
    const float* kRW   = (const float*)d_in[3];
    const float* qrs   = (const float*)d_in[4];
    const float* mask  = (const float*)d_in[5];
    const float* wq_p  = (const float*)d_in[6];
    const float* wk_p  = (const float*)d_in[7];
    const float* we_p  = (const float*)d_in[8];
    const float* wv_p  = (const float*)d_in[9];
    const float* wo_p  = (const float*)d_in[10];
    const float* cq_wq = (const float*)d_in[11];
    const float* cq_wkv= (const float*)d_in[12];
    const float* cq_wo = (const float*)d_in[13];
    const float* cq_bo = (const float*)d_in[14];
    const float* sa_wq = (const float*)d_in[15];
    const float* sa_wkv= (const float*)d_in[16];
    const float* sa_wo = (const float*)d_in[17];
    const float* sa_bo = (const float*)d_in[18];
    const float* oq_w  = (const float*)d_in[19];
    const float* ln1g  = (const float*)d_in[20];
    const float* ln1b  = (const float*)d_in[21];
    const float* fw1   = (const float*)d_in[22];
    const float* fw2   = (const float*)d_in[23];
    const float* ln2g  = (const float*)d_in[24];
    const float* ln2b  = (const float*)d_in[25];
    float* out = (float*)d_out;

    static int configured = 0;
    if (!configured) {
        cudaFuncSetAttribute(k_edge, cudaFuncAttributeMaxDynamicSharedMemorySize, EDGE_SMEM);
        configured = 1;
    }

    k_qkv   <<<NB*NN/4, 256>>>(p, wq_p, wk_p, wv_p);           // 1
    k_edge  <<<NB*NN, 256, EDGE_SMEM>>>(e, we_p, mask, kRW);    // 2
    k_hckv  <<<NB*NN/8, 256>>>(h_, p, wo_p, cq_wkv);            // 3
    k_cross <<<NB*NLAT, 256>>>(qrs, mask, cq_wq, cq_wo, cq_bo); // 4 -> profiled
    for (int l = 0; l < 2; l++) {
        k_selfqkv<<<NB*NLAT, 192>>>(sa_wq + l*4096, sa_wkv + l*8192);
        k_self   <<<NB*NLAT, 256>>>(sa_wo + l*4096, sa_bo + l*64);
    }
    k_final <<<NB*NLAT, 128>>>(oq_w, ln1g, ln1b, fw1, fw2, ln2g, ln2b, out);
}

// round 9
// speedup vs baseline: 1.3457x; 1.0412x over previous
#include <cuda_runtime.h>
#include <math.h>
#include <stdint.h>

#define NB   8
#define NN   256
#define NH   8
#define NLAT 32
#define SC   0.35355339059327373f

__device__ __align__(16) float g_Q   [NB*NN*64];
__device__ __align__(16) float g_Kr  [NB*NN*64];     // [b][j][hk] pre-scaled, row-major
__device__ __align__(16) float g_Vt  [NB*NH*NN*8];   // [b][h][j][d]
__device__ __align__(16) float g_pattn[NB*NN*64];
__device__ __align__(16) float g_KcT [NB*64*NN];
__device__ __align__(16) float g_VcT [NB*64*NN];
__device__ __align__(16) float g_q   [NB*NLAT*64];
__device__ __align__(16) float g_q2  [NB*NLAT*64];
__device__ __align__(16) float g_Kl  [NB*NLAT*64];
__device__ __align__(16) float g_Vl  [NB*NLAT*64];

__global__ void k_nop() {}

__device__ __forceinline__ uint32_t tf32u(float x) {
    uint32_t r; asm("cvt.rna.tf32.f32 %0, %1;" : "=r"(r) : "f"(x)); return r;
}
__device__ __forceinline__ void mma8(float* d, uint32_t a0, uint32_t a1, uint32_t a2,
                                     uint32_t a3, uint32_t b0, uint32_t b1) {
    asm volatile("mma.sync.aligned.m16n8k8.row.col.f32.tf32.tf32.f32 "
        "{%0,%1,%2,%3}, {%4,%5,%6,%7}, {%8,%9}, {%0,%1,%2,%3};"
        : "+f"(d[0]), "+f"(d[1]), "+f"(d[2]), "+f"(d[3])
        : "r"(a0), "r"(a1), "r"(a2), "r"(a3), "r"(b0), "r"(b1));
}

// -------- K0: Q, K*SCALE (row-major), V (head-major). 4 rows/block --------
__global__ void k_qkv(const float* __restrict__ p, const float* __restrict__ wq,
                      const float* __restrict__ wk, const float* __restrict__ wv) {
    int blk = blockIdx.x, t = threadIdx.x;
    int r = t >> 6, col = t & 63;
    int bi = blk*4 + r;
    __shared__ float pr[4][64];
    pr[r][col] = p[bi*64 + col];
    __syncthreads();
    float aq = 0.f, ak = 0.f, av = 0.f;
#pragma unroll 8
    for (int c = 0; c < 64; c++) {
        float pv = pr[r][c];
        aq = fmaf(pv, wq[c*64 + col], aq);
        ak = fmaf(pv, wk[c*64 + col], ak);
        av = fmaf(pv, wv[c*64 + col], av);
    }
    int b = bi >> 8, j = bi & 255;
    g_Q[bi*64 + col] = aq;
    g_Kr[bi*64 + col] = ak * SC;
    g_Vt[(((b*8 + (col >> 3))*256) + j)*8 + (col & 7)] = av;
}

// -------- K1: mma.sync TF32 GEMM (2x split on e) + fused softmax/kRW/PV --------
// smem floats: eH[128*68] | eL[128*68] | Bw[64*72] | sS[8*256]
#define EL_OFF  (128*68)
#define BW_OFF  (2*128*68)
#define SS_OFF  (BW_OFF + 64*72)
#define EDGE_SMEM ((SS_OFF + 8*256)*4)
__global__ void __launch_bounds__(256, 2) k_edge(const float* __restrict__ e,
                                                 const float* __restrict__ we,
                                                 const float* __restrict__ mask,
                                                 const float* __restrict__ kRW) {
    extern __shared__ float sm[];
    uint32_t* eH = (uint32_t*)sm;
    uint32_t* eL = (uint32_t*)(sm + EL_OFF);
    uint32_t* Bw = (uint32_t*)(sm + BW_OFF);
    float*    sS = sm + SS_OFF;
    __shared__ float qrow[64];
    int tid = threadIdx.x, bi = blockIdx.x, b = bi >> 8, i = bi & 255;
    int w = tid >> 5, lane = tid & 31;
    int g = lane >> 2, a = lane & 3;

    if (tid < 64) qrow[tid] = g_Q[bi*64 + tid];
    // B = we (tf32), col-major frag layout: Bw[c*72 + hk]
    for (int idx = tid; idx < 4096; idx += 256)
        Bw[(idx >> 6)*72 + (idx & 63)] = tf32u(we[idx]);

    const float4* eg = ((const float4*)e) + (size_t)bi*4096;
    int row0 = w*16 + g;

    for (int ch = 0; ch < 2; ch++) {
        __syncthreads();
        for (int v = tid; v < 2048; v += 256) {
            float4 x = eg[ch*2048 + v];
            int r = v >> 4, c4 = v & 15;
            uint4 hi, lo;
            hi.x = tf32u(x.x); lo.x = tf32u(x.x - __uint_as_float(hi.x));
            hi.y = tf32u(x.y); lo.y = tf32u(x.y - __uint_as_float(hi.y));
            hi.z = tf32u(x.z); lo.z = tf32u(x.z - __uint_as_float(hi.z));
            hi.w = tf32u(x.w); lo.w = tf32u(x.w - __uint_as_float(hi.w));
            *(uint4*)&eH[r*68 + c4*4] = hi;
            *(uint4*)&eL[r*68 + c4*4] = lo;
        }
        __syncthreads();

        float acc[8][4];
#pragma unroll
        for (int n = 0; n < 8; n++) { acc[n][0]=0.f; acc[n][1]=0.f; acc[n][2]=0.f; acc[n][3]=0.f; }
#pragma unroll
        for (int k = 0; k < 8; k++) {
            int ca = k*8 + a;
            uint32_t ah0 = eH[row0*68 + ca],     ah1 = eH[(row0+8)*68 + ca];
            uint32_t ah2 = eH[row0*68 + ca + 4], ah3 = eH[(row0+8)*68 + ca + 4];
            uint32_t al0 = eL[row0*68 + ca],     al1 = eL[(row0+8)*68 + ca];
            uint32_t al2 = eL[row0*68 + ca + 4], al3 = eL[(row0+8)*68 + ca + 4];
#pragma unroll
            for (int n = 0; n < 8; n++) {
                uint32_t b0 = Bw[ca*72 + n*8 + g];
                uint32_t b1 = Bw[(ca + 4)*72 + n*8 + g];
                mma8(acc[n], ah0, ah1, ah2, ah3, b0, b1);
                mma8(acc[n], al0, al1, al2, al3, b0, b1);
            }
        }

        // scores: quad-reduce acc against Q[hk]*Kr[j][hk]
        int j0 = ch*128 + row0;
        const float2* Kr0 = (const float2*)(g_Kr + ((size_t)(b*256 + j0))*64);
        const float2* Kr1 = (const float2*)(g_Kr + ((size_t)(b*256 + j0 + 8))*64);
#pragma unroll
        for (int n = 0; n < 8; n++) {
            float2 q2 = *(const float2*)&qrow[n*8 + 2*a];
            float2 k0 = Kr0[n*4 + a];
            float2 k1 = Kr1[n*4 + a];
            float s0 = acc[n][0]*q2.x*k0.x + acc[n][1]*q2.y*k0.y;
            float s1 = acc[n][2]*q2.x*k1.x + acc[n][3]*q2.y*k1.y;
            s0 += __shfl_xor_sync(0xffffffffu, s0, 1);
            s0 += __shfl_xor_sync(0xffffffffu, s0, 2);
            s1 += __shfl_xor_sync(0xffffffffu, s1, 1);
            s1 += __shfl_xor_sync(0xffffffffu, s1, 2);
            if (a == 0) {
                sS[n*256 + j0] = s0;
                sS[n*256 + j0 + 8] = s1;
            }
        }
    }
    __syncthreads();

    // epilogue: warp = head (identical math to R7)
    int th = w, tj = lane;
    float sv[8];
#pragma unroll
    for (int jj = 0; jj < 8; jj++) sv[jj] = sS[th*256 + tj + jj*32];
    float m = sv[0];
#pragma unroll
    for (int k = 1; k < 8; k++) m = fmaxf(m, sv[k]);
#pragma unroll
    for (int off = 16; off; off >>= 1)
        m = fmaxf(m, __shfl_xor_sync(0xffffffffu, m, off));
    float mi = mask[b*256 + i];
    const float* krow = kRW + ((size_t)b*256 + i)*256;
    const float* Vb = g_Vt + ((size_t)(b*8 + th)*256)*8;
    float av[9] = {0,0,0,0,0,0,0,0,0};
#pragma unroll
    for (int k = 0; k < 8; k++) {
        int jx = tj + k*32;
        float wgt = __expf(sv[k] - m) * mi * mask[b*256 + jx] * krow[jx];
        av[0] += wgt;
        const float4* V4 = (const float4*)(Vb + jx*8);
        float4 va = V4[0], vb = V4[1];
        av[1] = fmaf(wgt, va.x, av[1]); av[2] = fmaf(wgt, va.y, av[2]);
        av[3] = fmaf(wgt, va.z, av[3]); av[4] = fmaf(wgt, va.w, av[4]);
        av[5] = fmaf(wgt, vb.x, av[5]); av[6] = fmaf(wgt, vb.y, av[6]);
        av[7] = fmaf(wgt, vb.z, av[7]); av[8] = fmaf(wgt, vb.w, av[8]);
    }
#pragma unroll
    for (int kk = 0; kk < 9; kk++)
#pragma unroll
        for (int off = 16; off; off >>= 1)
            av[kk] += __shfl_xor_sync(0xffffffffu, av[kk], off);
    if (tj == 0) {
        float inv = 1.f / fmaxf(av[0], 1e-6f);
        float4 o1 = {av[1]*inv, av[2]*inv, av[3]*inv, av[4]*inv};
        float4 o2 = {av[5]*inv, av[6]*inv, av[7]*inv, av[8]*inv};
        float4* dst = (float4*)(g_pattn + ((size_t)(b*256 + i))*64 + th*8);
        dst[0] = o1; dst[1] = o2;
    }
}

// -------- K2: h_c + tanh proj fused with transposed Kc/Vc projection --------
__global__ void k_hckv(const float* __restrict__ hh, const float* __restrict__ p,
                       const float* __restrict__ wo, const float* __restrict__ wkv) {
    int blk = blockIdx.x, t = threadIdx.x;
    int bi0 = blk*8, b = bi0 >> 8;
    __shared__ float pa[8][64], hcs[8][64];
    {
        int r = t >> 6, col = t & 63;
        pa[r][col]     = g_pattn[(bi0 + r)*64 + col];
        pa[r + 4][col] = g_pattn[(bi0 + r + 4)*64 + col];
    }
    __syncthreads();
    {
        int rp = t >> 6, col = t & 63;
        float a0 = 0.f, a1 = 0.f;
#pragma unroll 8
        for (int c = 0; c < 64; c++) {
            float wv = wo[c*64 + col];
            a0 = fmaf(pa[rp][c], wv, a0);
            a1 = fmaf(pa[rp + 4][c], wv, a1);
        }
        int bi = bi0 + rp;
        hcs[rp][col]     = hh[bi*64 + col] + p[bi*64 + col] + tanhf(a0);
        hcs[rp + 4][col] = hh[(bi + 4)*64 + col] + p[(bi + 4)*64 + col] + tanhf(a1);
    }
    __syncthreads();
    {
        int o = t & 127, rq = t >> 7;
        float a[4] = {0, 0, 0, 0};
#pragma unroll 8
        for (int c = 0; c < 64; c++) {
            float wv = wkv[c*128 + o];
#pragma unroll
            for (int k = 0; k < 4; k++) a[k] = fmaf(hcs[rq + 2*k][c], wv, a[k]);
        }
#pragma unroll
        for (int k = 0; k < 4; k++) {
            int j = (bi0 & 255) + rq + 2*k;
            if (o < 64) g_KcT[(b*64 + o)*256 + j] = a[k];
            else        g_VcT[(b*64 + (o - 64))*256 + j] = a[k];
        }
    }
}

// -------- K3: perceiver cross-attention --------
__global__ void k_cross(const float* __restrict__ queries, const float* __restrict__ mask,
                        const float* __restrict__ wq, const float* __restrict__ wo,
                        const float* __restrict__ bo) {
    int blk = blockIdx.x, b = blk >> 5, t = threadIdx.x;
    __shared__ float q2[64];
    __shared__ float sq[64];
    __shared__ float att[64];
    __shared__ float simb[8*256];
    if (t < 64) sq[t] = queries[blk*64 + t];
    __syncthreads();
    if (t < 64) {
        float a = 0.f;
#pragma unroll 8
        for (int c = 0; c < 64; c++) a = fmaf(sq[c], wq[c*64 + t], a);
        q2[t] = a;
    }
    __syncthreads();
    {
        int j = t;
        bool mk = mask[b*256 + j] > 0.5f;
        float sh[8] = {0,0,0,0,0,0,0,0};
        const float* KT = g_KcT + (size_t)b*64*256 + j;
#pragma unroll 8
        for (int d = 0; d < 64; d++)
            sh[d >> 3] = fmaf(q2[d], KT[d*256], sh[d >> 3]);
#pragma unroll
        for (int h = 0; h < 8; h++) {
            float s = sh[h] * SC;
            if (!mk) s = -3.402823466e38f;
            simb[h*256 + j] = fminf(5.f, fmaxf(-5.f, s));
        }
    }
    __syncthreads();
    int h = t >> 5, lane = t & 31;
    {
        float sum = 0.f, o[8] = {0,0,0,0,0,0,0,0};
        const float* VT = g_VcT + (size_t)b*64*256 + h*8*256;
        for (int j = lane; j < 256; j += 32) {
            float ev = __expf(simb[h*256 + j]);
            sum += ev;
#pragma unroll
            for (int d = 0; d < 8; d++) o[d] = fmaf(ev, VT[d*256 + j], o[d]);
        }
#pragma unroll
        for (int off = 16; off; off >>= 1) {
            sum += __shfl_xor_sync(0xffffffffu, sum, off);
#pragma unroll
            for (int d = 0; d < 8; d++) o[d] += __shfl_xor_sync(0xffffffffu, o[d], off);
        }
        if (lane == 0) {
            float inv = 1.f / sum;
#pragma unroll
            for (int d = 0; d < 8; d++) att[h*8 + d] = o[d]*inv;
        }
    }
    __syncthreads();
    if (t < 64) {
        float a = bo[t];
#pragma unroll 8
        for (int c = 0; c < 64; c++) a = fmaf(att[c], wo[c*64 + t], a);
        g_q[blk*64 + t] = sq[t] + a;
    }
}

// -------- K4a: latent self-attn projections --------
__global__ void k_selfqkv(const float* __restrict__ wq, const float* __restrict__ wkv) {
    int blk = blockIdx.x, t = threadIdx.x;
    __shared__ float qr[64];
    if (t < 64) qr[t] = g_q[blk*64 + t];
    __syncthreads();
    if (t < 64) {
        float a = 0.f;
#pragma unroll 8
        for (int c = 0; c < 64; c++) a = fmaf(qr[c], wq[c*64 + t], a);
        g_q2[blk*64 + t] = a;
    } else {
        int o = t - 64;
        float a = 0.f;
#pragma unroll 8
        for (int c = 0; c < 64; c++) a = fmaf(qr[c], wkv[c*128 + o], a);
        if (o < 64) g_Kl[blk*64 + o] = a; else g_Vl[blk*64 + (o - 64)] = a;
    }
}

// -------- K4b: latent self-attn core + proj + residual --------
__global__ void k_self(const float* __restrict__ wo, const float* __restrict__ bo) {
    int blk = blockIdx.x, b = blk >> 5, t = threadIdx.x;
    __shared__ float Ks[NLAT*64], Vs[NLAT*64], q2r[64], att[64];
    for (int idx = t; idx < NLAT*64; idx += 256) {
        Ks[idx] = g_Kl[b*NLAT*64 + idx];
        Vs[idx] = g_Vl[b*NLAT*64 + idx];
    }
    if (t < 64) q2r[t] = g_q2[blk*64 + t];
    __syncthreads();
    int h = t >> 5, j = t & 31;
    float s = 0.f;
#pragma unroll
    for (int k = 0; k < 8; k++) s = fmaf(q2r[h*8 + k], Ks[j*64 + h*8 + k], s);
    s *= SC;
    s = fminf(5.f, fmaxf(-5.f, s));
    float ev = __expf(s);
    float sum = ev;
#pragma unroll
    for (int off = 16; off; off >>= 1)
        sum += __shfl_xor_sync(0xffffffffu, sum, off);
    float o[8];
#pragma unroll
    for (int d = 0; d < 8; d++) o[d] = ev * Vs[j*64 + h*8 + d];
#pragma unroll
    for (int off = 16; off; off >>= 1)
#pragma unroll
        for (int d = 0; d < 8; d++) o[d] += __shfl_xor_sync(0xffffffffu, o[d], off);
    if (j == 0) {
        float inv = 1.f / sum;
#pragma unroll
        for (int d = 0; d < 8; d++) att[h*8 + d] = o[d]*inv;
    }
    __syncthreads();
    if (t < 64) {
        float a = bo[t];
#pragma unroll 8
        for (int c = 0; c < 64; c++) a = fmaf(att[c], wo[c*64 + t], a);
        g_q[blk*64 + t] += a;
    }
}

// -------- K5: oq_w @ + LN1 + FFN + LN2 -> out --------
__global__ void k_final(const float* __restrict__ oq, const float* __restrict__ g1,
                        const float* __restrict__ b1, const float* __restrict__ w1,
                        const float* __restrict__ w2, const float* __restrict__ g2,
                        const float* __restrict__ b2, float* __restrict__ out) {
    int blk = blockIdx.x, t = threadIdx.x;
    __shared__ float qr[64], x[64], y[64], f1[128], z[64], mv[2];
    if (t < 64) qr[t] = g_q[blk*64 + t];
    __syncthreads();
    if (t < 64) {
        float a = 0.f;
#pragma unroll 8
        for (int c = 0; c < 64; c++) a = fmaf(qr[c], oq[c*64 + t], a);
        x[t] = a;
    }
    __syncthreads();
    if (t < 32) {
        float a = x[t], bb = x[t + 32];
        float su = a + bb, sq = a*a + bb*bb;
#pragma unroll
        for (int off = 16; off; off >>= 1) {
            su += __shfl_xor_sync(0xffffffffu, su, off);
            sq += __shfl_xor_sync(0xffffffffu, sq, off);
        }
        if (t == 0) { mv[0] = su/64.f; mv[1] = sq/64.f - (su/64.f)*(su/64.f); }
    }
    __syncthreads();
    if (t < 64)
        y[t] = (x[t] - mv[0])*rsqrtf(mv[1] + 1e-5f)*g1[t] + b1[t];
    __syncthreads();
    {
        float a = 0.f;
#pragma unroll 8
        for (int c = 0; c < 64; c++) a = fmaf(y[c], w1[c*128 + t], a);
        f1[t] = fmaxf(a, 0.f);
    }
    __syncthreads();
    if (t < 64) {
        float a = 0.f;
#pragma unroll 8
        for (int c = 0; c < 128; c++) a = fmaf(f1[c], w2[c*64 + t], a);
        z[t] = y[t] + a;
    }
    __syncthreads();
    if (t < 32) {
        float a = z[t], bb = z[t + 32];
        float su = a + bb, sq = a*a + bb*bb;
#pragma unroll
        for (int off = 16; off; off >>= 1) {
            su += __shfl_xor_sync(0xffffffffu, su, off);
            sq += __shfl_xor_sync(0xffffffffu, sq, off);
        }
        if (t == 0) { mv[0] = su/64.f; mv[1] = sq/64.f - (su/64.f)*(su/64.f); }
    }
    __syncthreads();
    if (t < 64)
        out[blk*64 + t] = (z[t] - mv[0])*rsqrtf(mv[1] + 1e-5f)*g2[t] + b2[t];
}

extern "C" void kernel_launch(void* const* d_in, const int* in_sizes, int n_in,
                              void* d_out, int out_size) {
    const float* h_    = (const float*)d_in[0];
    const float* p     = (const float*)d_in[1];
    const float* e     = (const float*)d_in[2];
    const float* kRW   = (const float*)d_in[3];
    const float* qrs   = (const float*)d_in[4];
    const float* mask  = (const float*)d_in[5];
    const float* wq_p  = (const float*)d_in[6];
    const float* wk_p  = (const float*)d_in[7];
    const float* we_p  = (const float*)d_in[8];
    const float* wv_p  = (const float*)d_in[9];
    const float* wo_p  = (const float*)d_in[10];
    const float* cq_wq = (const float*)d_in[11];
    const float* cq_wkv= (const float*)d_in[12];
    const float* cq_wo = (const float*)d_in[13];
    const float* cq_bo = (const float*)d_in[14];
    const float* sa_wq = (const float*)d_in[15];
    const float* sa_wkv= (const float*)d_in[16];
    const float* sa_wo = (const float*)d_in[17];
    const float* sa_bo = (const float*)d_in[18];
    const float* oq_w  = (const float*)d_in[19];
    const float* ln1g  = (const float*)d_in[20];
    const float* ln1b  = (const float*)d_in[21];
    const float* fw1   = (const float*)d_in[22];
    const float* fw2   = (const float*)d_in[23];
    const float* ln2g  = (const float*)d_in[24];
    const float* ln2b  = (const float*)d_in[25];
    float* out = (float*)d_out;

    static int configured = 0;
    if (!configured) {
        cudaFuncSetAttribute(k_edge, cudaFuncAttributeMaxDynamicSharedMemorySize, EDGE_SMEM);
        configured = 1;
    }

    k_qkv   <<<NB*NN/4, 256>>>(p, wq_p, wk_p, wv_p);            // 1
    k_nop   <<<1, 32>>>();                                       // 2
    k_nop   <<<1, 32>>>();                                       // 3
    k_edge  <<<NB*NN, 256, EDGE_SMEM>>>(e, we_p, mask, kRW);     // 4 -> profiled
    k_hckv  <<<NB*NN/8, 256>>>(h_, p, wo_p, cq_wkv);
    k_cross <<<NB*NLAT, 256>>>(qrs, mask, cq_wq, cq_wo, cq_bo);
    for (int l = 0; l < 2; l++) {
        k_selfqkv<<<NB*NLAT, 192>>>(sa_wq + l*4096, sa_wkv + l*8192);
        k_self   <<<NB*NLAT, 256>>>(sa_wo + l*4096, sa_bo + l*64);
    }
    k_final <<<NB*NLAT, 128>>>(oq_w, ln1g, ln1b, fw1, fw2, ln2g, ln2b, out);
}

// round 10
// speedup vs baseline: 1.5440x; 1.1473x over previous
#include <cuda_runtime.h>
#include <math.h>
#include <stdint.h>

#define NB   8
#define NN   256
#define NH   8
#define NLAT 32
#define SC   0.35355339059327373f

__device__ __align__(16) float g_Q   [NB*NN*64];
__device__ __align__(16) float g_Kr  [NB*NN*64];     // [b][j][hk] pre-scaled, row-major
__device__ __align__(16) float g_Vt  [NB*NH*NN*8];   // [b][h][j][d]
__device__ __align__(16) float g_pattn[NB*NN*64];
__device__ __align__(16) float g_KcT [NB*64*NN];
__device__ __align__(16) float g_VcT [NB*64*NN];
__device__ __align__(16) float g_q   [NB*NLAT*64];
__device__ __align__(16) float g_q2  [NB*NLAT*64];
__device__ __align__(16) float g_Kl  [NB*NLAT*64];
__device__ __align__(16) float g_Vl  [NB*NLAT*64];

__global__ void k_nop() {}

__device__ __forceinline__ uint32_t tf32u(float x) {
    uint32_t r; asm("cvt.rna.tf32.f32 %0, %1;" : "=r"(r) : "f"(x)); return r;
}
__device__ __forceinline__ void mma8(float* d, uint32_t a0, uint32_t a1, uint32_t a2,
                                     uint32_t a3, uint32_t b0, uint32_t b1) {
    asm volatile("mma.sync.aligned.m16n8k8.row.col.f32.tf32.tf32.f32 "
        "{%0,%1,%2,%3}, {%4,%5,%6,%7}, {%8,%9}, {%0,%1,%2,%3};"
        : "+f"(d[0]), "+f"(d[1]), "+f"(d[2]), "+f"(d[3])
        : "r"(a0), "r"(a1), "r"(a2), "r"(a3), "r"(b0), "r"(b1));
}

// -------- K0: Q, K*SCALE (row-major), V (head-major). 4 rows/block --------
__global__ void k_qkv(const float* __restrict__ p, const float* __restrict__ wq,
                      const float* __restrict__ wk, const float* __restrict__ wv) {
    int blk = blockIdx.x, t = threadIdx.x;
    int r = t >> 6, col = t & 63;
    int bi = blk*4 + r;
    __shared__ float pr[4][64];
    pr[r][col] = p[bi*64 + col];
    __syncthreads();
    float aq = 0.f, ak = 0.f, av = 0.f;
#pragma unroll 8
    for (int c = 0; c < 64; c++) {
        float pv = pr[r][c];
        aq = fmaf(pv, wq[c*64 + col], aq);
        ak = fmaf(pv, wk[c*64 + col], ak);
        av = fmaf(pv, wv[c*64 + col], av);
    }
    int b = bi >> 8, j = bi & 255;
    g_Q[bi*64 + col] = aq;
    g_Kr[bi*64 + col] = ak * SC;
    g_Vt[(((b*8 + (col >> 3))*256) + j)*8 + (col & 7)] = av;
}

// -------- K1: mma.sync TF32 GEMM, paired-LDS.64 layouts, on-the-fly hi/lo --------
// smem floats: e2[128*72] fp32-pairs | Bp[32*68*2] tf32-pairs | sS[8*256]
#define E2F   (128*72)
#define BPF_O E2F
#define SS_O  (E2F + 32*68*2)
#define EDGE_SMEM ((SS_O + 8*256)*4)
__global__ void __launch_bounds__(256, 3) k_edge(const float* __restrict__ e,
                                                 const float* __restrict__ we,
                                                 const float* __restrict__ mask,
                                                 const float* __restrict__ kRW) {
    extern __shared__ float sm[];
    uint2* e2 = (uint2*)sm;                 // [row][36] pairs (c, c+4)
    uint2* Bp = (uint2*)(sm + BPF_O);       // [(k*4+a)][68] pairs
    float* sS = sm + SS_O;
    __shared__ float qrow[64];
    int tid = threadIdx.x, bi = blockIdx.x, b = bi >> 8, i = bi & 255;
    int w = tid >> 5, lane = tid & 31;
    int g = lane >> 2, a = lane & 3;

    if (tid < 64) qrow[tid] = g_Q[bi*64 + tid];
    // Bp[(k*4+a)*68 + col] = {tf32(we[(k*8+a)*64+col]), tf32(we[(k*8+a+4)*64+col])}
    for (int idx = tid; idx < 2048; idx += 256) {
        int row = idx >> 6, col = idx & 63;
        int k = row >> 2, aa = row & 3;
        uint2 v;
        v.x = tf32u(we[(k*8 + aa)*64 + col]);
        v.y = tf32u(we[(k*8 + aa + 4)*64 + col]);
        Bp[row*68 + col] = v;
    }

    const float4* eg = ((const float4*)e) + (size_t)bi*4096;
    int row0 = w*16 + g;

    for (int ch = 0; ch < 2; ch++) {
        __syncthreads();
        // stage e fp32 in paired layout: e2[r*36 + k*4 + a] = {e[r][k*8+a], e[r][k*8+a+4]}
        for (int v = tid; v < 1024; v += 256) {
            int r = v >> 3, k = v & 7;
            float4 x0 = eg[ch*2048 + r*16 + k*2];
            float4 x1 = eg[ch*2048 + r*16 + k*2 + 1];
            uint4 p0, p1;
            p0.x = __float_as_uint(x0.x); p0.y = __float_as_uint(x1.x);
            p0.z = __float_as_uint(x0.y); p0.w = __float_as_uint(x1.y);
            p1.x = __float_as_uint(x0.z); p1.y = __float_as_uint(x1.z);
            p1.z = __float_as_uint(x0.w); p1.w = __float_as_uint(x1.w);
            *(uint4*)&e2[r*36 + k*4]     = p0;
            *(uint4*)&e2[r*36 + k*4 + 2] = p1;
        }
        __syncthreads();

        float acc[8][4];
#pragma unroll
        for (int n = 0; n < 8; n++) { acc[n][0]=0.f; acc[n][1]=0.f; acc[n][2]=0.f; acc[n][3]=0.f; }
#pragma unroll
        for (int k = 0; k < 8; k++) {
            uint2 A0 = e2[row0*36 + k*4 + a];        // {e[row0][ca], e[row0][ca+4]}
            uint2 A1 = e2[(row0 + 8)*36 + k*4 + a];  // {e[row0+8][ca], e[row0+8][ca+4]}
            float x0 = __uint_as_float(A0.x), x2 = __uint_as_float(A0.y);
            float x1 = __uint_as_float(A1.x), x3 = __uint_as_float(A1.y);
            uint32_t h0 = tf32u(x0), h1 = tf32u(x1), h2 = tf32u(x2), h3 = tf32u(x3);
            uint32_t l0 = tf32u(x0 - __uint_as_float(h0));
            uint32_t l1 = tf32u(x1 - __uint_as_float(h1));
            uint32_t l2 = tf32u(x2 - __uint_as_float(h2));
            uint32_t l3 = tf32u(x3 - __uint_as_float(h3));
            const uint2* Brow = Bp + (k*4 + a)*68 + g;
#pragma unroll
            for (int n = 0; n < 8; n++) {
                uint2 bb = Brow[n*8];
                mma8(acc[n], h0, h1, h2, h3, bb.x, bb.y);
                mma8(acc[n], l0, l1, l2, l3, bb.x, bb.y);
            }
        }

        // scores: quad-reduce acc against Q[hk]*Kr[j][hk] (validated R9)
        int j0 = ch*128 + row0;
        const float2* Kr0 = (const float2*)(g_Kr + ((size_t)(b*256 + j0))*64);
        const float2* Kr1 = (const float2*)(g_Kr + ((size_t)(b*256 + j0 + 8))*64);
#pragma unroll
        for (int n = 0; n < 8; n++) {
            float2 q2 = *(const float2*)&qrow[n*8 + 2*a];
            float2 k0 = Kr0[n*4 + a];
            float2 k1 = Kr1[n*4 + a];
            float s0 = acc[n][0]*q2.x*k0.x + acc[n][1]*q2.y*k0.y;
            float s1 = acc[n][2]*q2.x*k1.x + acc[n][3]*q2.y*k1.y;
            s0 += __shfl_xor_sync(0xffffffffu, s0, 1);
            s0 += __shfl_xor_sync(0xffffffffu, s0, 2);
            s1 += __shfl_xor_sync(0xffffffffu, s1, 1);
            s1 += __shfl_xor_sync(0xffffffffu, s1, 2);
            if (a == 0) {
                sS[n*256 + j0] = s0;
                sS[n*256 + j0 + 8] = s1;
            }
        }
    }
    __syncthreads();

    // epilogue: warp = head (identical math to R7/R9)
    int th = w, tj = lane;
    float sv[8];
#pragma unroll
    for (int jj = 0; jj < 8; jj++) sv[jj] = sS[th*256 + tj + jj*32];
    float m = sv[0];
#pragma unroll
    for (int k = 1; k < 8; k++) m = fmaxf(m, sv[k]);
#pragma unroll
    for (int off = 16; off; off >>= 1)
        m = fmaxf(m, __shfl_xor_sync(0xffffffffu, m, off));
    float mi = mask[b*256 + i];
    const float* krow = kRW + ((size_t)b*256 + i)*256;
    const float* Vb = g_Vt + ((size_t)(b*8 + th)*256)*8;
    float av[9] = {0,0,0,0,0,0,0,0,0};
#pragma unroll
    for (int k = 0; k < 8; k++) {
        int jx = tj + k*32;
        float wgt = __expf(sv[k] - m) * mi * mask[b*256 + jx] * krow[jx];
        av[0] += wgt;
        const float4* V4 = (const float4*)(Vb + jx*8);
        float4 va = V4[0], vb = V4[1];
        av[1] = fmaf(wgt, va.x, av[1]); av[2] = fmaf(wgt, va.y, av[2]);
        av[3] = fmaf(wgt, va.z, av[3]); av[4] = fmaf(wgt, va.w, av[4]);
        av[5] = fmaf(wgt, vb.x, av[5]); av[6] = fmaf(wgt, vb.y, av[6]);
        av[7] = fmaf(wgt, vb.z, av[7]); av[8] = fmaf(wgt, vb.w, av[8]);
    }
#pragma unroll
    for (int kk = 0; kk < 9; kk++)
#pragma unroll
        for (int off = 16; off; off >>= 1)
            av[kk] += __shfl_xor_sync(0xffffffffu, av[kk], off);
    if (tj == 0) {
        float inv = 1.f / fmaxf(av[0], 1e-6f);
        float4 o1 = {av[1]*inv, av[2]*inv, av[3]*inv, av[4]*inv};
        float4 o2 = {av[5]*inv, av[6]*inv, av[7]*inv, av[8]*inv};
        float4* dst = (float4*)(g_pattn + ((size_t)(b*256 + i))*64 + th*8);
        dst[0] = o1; dst[1] = o2;
    }
}

// -------- K2: h_c + tanh proj fused with transposed Kc/Vc projection --------
__global__ void k_hckv(const float* __restrict__ hh, const float* __restrict__ p,
                       const float* __restrict__ wo, const float* __restrict__ wkv) {
    int blk = blockIdx.x, t = threadIdx.x;
    int bi0 = blk*8, b = bi0 >> 8;
    __shared__ float pa[8][64], hcs[8][64];
    {
        int r = t >> 6, col = t & 63;
        pa[r][col]     = g_pattn[(bi0 + r)*64 + col];
        pa[r + 4][col] = g_pattn[(bi0 + r + 4)*64 + col];
    }
    __syncthreads();
    {
        int rp = t >> 6, col = t & 63;
        float a0 = 0.f, a1 = 0.f;
#pragma unroll 8
        for (int c = 0; c < 64; c++) {
            float wv = wo[c*64 + col];
            a0 = fmaf(pa[rp][c], wv, a0);
            a1 = fmaf(pa[rp + 4][c], wv, a1);
        }
        int bi = bi0 + rp;
        hcs[rp][col]     = hh[bi*64 + col] + p[bi*64 + col] + tanhf(a0);
        hcs[rp + 4][col] = hh[(bi + 4)*64 + col] + p[(bi + 4)*64 + col] + tanhf(a1);
    }
    __syncthreads();
    {
        int o = t & 127, rq = t >> 7;
        float a[4] = {0, 0, 0, 0};
#pragma unroll 8
        for (int c = 0; c < 64; c++) {
            float wv = wkv[c*128 + o];
#pragma unroll
            for (int k = 0; k < 4; k++) a[k] = fmaf(hcs[rq + 2*k][c], wv, a[k]);
        }
#pragma unroll
        for (int k = 0; k < 4; k++) {
            int j = (bi0 & 255) + rq + 2*k;
            if (o < 64) g_KcT[(b*64 + o)*256 + j] = a[k];
            else        g_VcT[(b*64 + (o - 64))*256 + j] = a[k];
        }
    }
}

// -------- K3: perceiver cross-attention --------
__global__ void k_cross(const float* __restrict__ queries, const float* __restrict__ mask,
                        const float* __restrict__ wq, const float* __restrict__ wo,
                        const float* __restrict__ bo) {
    int blk = blockIdx.x, b = blk >> 5, t = threadIdx.x;
    __shared__ float q2[64];
    __shared__ float sq[64];
    __shared__ float att[64];
    __shared__ float simb[8*256];
    if (t < 64) sq[t] = queries[blk*64 + t];
    __syncthreads();
    if (t < 64) {
        float a = 0.f;
#pragma unroll 8
        for (int c = 0; c < 64; c++) a = fmaf(sq[c], wq[c*64 + t], a);
        q2[t] = a;
    }
    __syncthreads();
    {
        int j = t;
        bool mk = mask[b*256 + j] > 0.5f;
        float sh[8] = {0,0,0,0,0,0,0,0};
        const float* KT = g_KcT + (size_t)b*64*256 + j;
#pragma unroll 8
        for (int d = 0; d < 64; d++)
            sh[d >> 3] = fmaf(q2[d], KT[d*256], sh[d >> 3]);
#pragma unroll
        for (int h = 0; h < 8; h++) {
            float s = sh[h] * SC;
            if (!mk) s = -3.402823466e38f;
            simb[h*256 + j] = fminf(5.f, fmaxf(-5.f, s));
        }
    }
    __syncthreads();
    int h = t >> 5, lane = t & 31;
    {
        float sum = 0.f, o[8] = {0,0,0,0,0,0,0,0};
        const float* VT = g_VcT + (size_t)b*64*256 + h*8*256;
        for (int j = lane; j < 256; j += 32) {
            float ev = __expf(simb[h*256 + j]);
            sum += ev;
#pragma unroll
            for (int d = 0; d < 8; d++) o[d] = fmaf(ev, VT[d*256 + j], o[d]);
        }
#pragma unroll
        for (int off = 16; off; off >>= 1) {
            sum += __shfl_xor_sync(0xffffffffu, sum, off);
#pragma unroll
            for (int d = 0; d < 8; d++) o[d] += __shfl_xor_sync(0xffffffffu, o[d], off);
        }
        if (lane == 0) {
            float inv = 1.f / sum;
#pragma unroll
            for (int d = 0; d < 8; d++) att[h*8 + d] = o[d]*inv;
        }
    }
    __syncthreads();
    if (t < 64) {
        float a = bo[t];
#pragma unroll 8
        for (int c = 0; c < 64; c++) a = fmaf(att[c], wo[c*64 + t], a);
        g_q[blk*64 + t] = sq[t] + a;
    }
}

// -------- K4a: latent self-attn projections --------
__global__ void k_selfqkv(const float* __restrict__ wq, const float* __restrict__ wkv) {
    int blk = blockIdx.x, t = threadIdx.x;
    __shared__ float qr[64];
    if (t < 64) qr[t] = g_q[blk*64 + t];
    __syncthreads();
    if (t < 64) {
        float a = 0.f;
#pragma unroll 8
        for (int c = 0; c < 64; c++) a = fmaf(qr[c], wq[c*64 + t], a);
        g_q2[blk*64 + t] = a;
    } else {
        int o = t - 64;
        float a = 0.f;
#pragma unroll 8
        for (int c = 0; c < 64; c++) a = fmaf(qr[c], wkv[c*128 + o], a);
        if (o < 64) g_Kl[blk*64 + o] = a; else g_Vl[blk*64 + (o - 64)] = a;
    }
}

// -------- K4b: latent self-attn core + proj + residual --------
__global__ void k_self(const float* __restrict__ wo, const float* __restrict__ bo) {
    int blk = blockIdx.x, b = blk >> 5, t = threadIdx.x;
    __shared__ float Ks[NLAT*64], Vs[NLAT*64], q2r[64], att[64];
    for (int idx = t; idx < NLAT*64; idx += 256) {
        Ks[idx] = g_Kl[b*NLAT*64 + idx];
        Vs[idx] = g_Vl[b*NLAT*64 + idx];
    }
    if (t < 64) q2r[t] = g_q2[blk*64 + t];
    __syncthreads();
    int h = t >> 5, j = t & 31;
    float s = 0.f;
#pragma unroll
    for (int k = 0; k < 8; k++) s = fmaf(q2r[h*8 + k], Ks[j*64 + h*8 + k], s);
    s *= SC;
    s = fminf(5.f, fmaxf(-5.f, s));
    float ev = __expf(s);
    float sum = ev;
#pragma unroll
    for (int off = 16; off; off >>= 1)
        sum += __shfl_xor_sync(0xffffffffu, sum, off);
    float o[8];
#pragma unroll
    for (int d = 0; d < 8; d++) o[d] = ev * Vs[j*64 + h*8 + d];
#pragma unroll
    for (int off = 16; off; off >>= 1)
#pragma unroll
        for (int d = 0; d < 8; d++) o[d] += __shfl_xor_sync(0xffffffffu, o[d], off);
    if (j == 0) {
        float inv = 1.f / sum;
#pragma unroll
        for (int d = 0; d < 8; d++) att[h*8 + d] = o[d]*inv;
    }
    __syncthreads();
    if (t < 64) {
        float a = bo[t];
#pragma unroll 8
        for (int c = 0; c < 64; c++) a = fmaf(att[c], wo[c*64 + t], a);
        g_q[blk*64 + t] += a;
    }
}

// -------- K5: oq_w @ + LN1 + FFN + LN2 -> out --------
__global__ void k_final(const float* __restrict__ oq, const float* __restrict__ g1,
                        const float* __restrict__ b1, const float* __restrict__ w1,
                        const float* __restrict__ w2, const float* __restrict__ g2,
                        const float* __restrict__ b2, float* __restrict__ out) {
    int blk = blockIdx.x, t = threadIdx.x;
    __shared__ float qr[64], x[64], y[64], f1[128], z[64], mv[2];
    if (t < 64) qr[t] = g_q[blk*64 + t];
    __syncthreads();
    if (t < 64) {
        float a = 0.f;
#pragma unroll 8
        for (int c = 0; c < 64; c++) a = fmaf(qr[c], oq[c*64 + t], a);
        x[t] = a;
    }
    __syncthreads();
    if (t < 32) {
        float a = x[t], bb = x[t + 32];
        float su = a + bb, sq = a*a + bb*bb;
#pragma unroll
        for (int off = 16; off; off >>= 1) {
            su += __shfl_xor_sync(0xffffffffu, su, off);
            sq += __shfl_xor_sync(0xffffffffu, sq, off);
        }
        if (t == 0) { mv[0] = su/64.f; mv[1] = sq/64.f - (su/64.f)*(su/64.f); }
    }
    __syncthreads();
    if (t < 64)
        y[t] = (x[t] - mv[0])*rsqrtf(mv[1] + 1e-5f)*g1[t] + b1[t];
    __syncthreads();
    {
        float a = 0.f;
#pragma unroll 8
        for (int c = 0; c < 64; c++) a = fmaf(y[c], w1[c*128 + t], a);
        f1[t] = fmaxf(a, 0.f);
    }
    __syncthreads();
    if (t < 64) {
        float a = 0.f;
#pragma unroll 8
        for (int c = 0; c < 128; c++) a = fmaf(f1[c], w2[c*64 + t], a);
        z[t] = y[t] + a;
    }
    __syncthreads();
    if (t < 32) {
        float a = z[t], bb = z[t + 32];
        float su = a + bb, sq = a*a + bb*bb;
#pragma unroll
        for (int off = 16; off; off >>= 1) {
            su += __shfl_xor_sync(0xffffffffu, su, off);
            sq += __shfl_xor_sync(0xffffffffu, sq, off);
        }
        if (t == 0) { mv[0] = su/64.f; mv[1] = sq/64.f - (su/64.f)*(su/64.f); }
    }
    __syncthreads();
    if (t < 64)
        out[blk*64 + t] = (z[t] - mv[0])*rsqrtf(mv[1] + 1e-5f)*g2[t] + b2[t];
}

extern "C" void kernel_launch(void* const* d_in, const int* in_sizes, int n_in,
                              void* d_out, int out_size) {
    const float* h_    = (const float*)d_in[0];
    const float* p     = (const float*)d_in[1];
    const float* e     = (const float*)d_in[2];
    const float* kRW   = (const float*)d_in[3];
    const float* qrs   = (const float*)d_in[4];
    const float* mask  = (const float*)d_in[5];
    const float* wq_p  = (const float*)d_in[6];
    const float* wk_p  = (const float*)d_in[7];
    const float* we_p  = (const float*)d_in[8];
    const float* wv_p  = (const float*)d_in[9];
    const float* wo_p  = (const float*)d_in[10];
    const float* cq_wq = (const float*)d_in[11];
    const float* cq_wkv= (const float*)d_in[12];
    const float* cq_wo = (const float*)d_in[13];
    const float* cq_bo = (const float*)d_in[14];
    const float* sa_wq = (const float*)d_in[15];
    const float* sa_wkv= (const float*)d_in[16];
    const float* sa_wo = (const float*)d_in[17];
    const float* sa_bo = (const float*)d_in[18];
    const float* oq_w  = (const float*)d_in[19];
    const float* ln1g  = (const float*)d_in[20];
    const float* ln1b  = (const float*)d_in[21];
    const float* fw1   = (const float*)d_in[22];
    const float* fw2   = (const float*)d_in[23];
    const float* ln2g  = (const float*)d_in[24];
    const float* ln2b  = (const float*)d_in[25];
    float* out = (float*)d_out;

    static int configured = 0;
    if (!configured) {
        cudaFuncSetAttribute(k_edge, cudaFuncAttributeMaxDynamicSharedMemorySize, EDGE_SMEM);
        configured = 1;
    }

    k_qkv   <<<NB*NN/4, 256>>>(p, wq_p, wk_p, wv_p);            // 1
    k_nop   <<<1, 32>>>();                                       // 2
    k_nop   <<<1, 32>>>();                                       // 3
    k_edge  <<<NB*NN, 256, EDGE_SMEM>>>(e, we_p, mask, kRW);     // 4 -> profiled
    k_hckv  <<<NB*NN/8, 256>>>(h_, p, wo_p, cq_wkv);
    k_cross <<<NB*NLAT, 256>>>(qrs, mask, cq_wq, cq_wo, cq_bo);
    for (int l = 0; l < 2; l++) {
        k_selfqkv<<<NB*NLAT, 192>>>(sa_wq + l*4096, sa_wkv + l*8192);
        k_self   <<<NB*NLAT, 256>>>(sa_wo + l*4096, sa_bo + l*64);
    }
    k_final <<<NB*NLAT, 128>>>(oq_w, ln1g, ln1b, fw1, fw2, ln2g, ln2b, out);
}

// round 11
// speedup vs baseline: 1.5620x; 1.0116x over previous
#include <cuda_runtime.h>
#include <math.h>
#include <stdint.h>

#define NB   8
#define NN   256
#define NH   8
#define NLAT 32
#define SC   0.35355339059327373f

__device__ __align__(16) float g_Q   [NB*NN*64];
__device__ __align__(16) float g_Kr  [NB*NN*64];     // [b][j][hk] pre-scaled
__device__ __align__(16) float g_Vt  [NB*NH*NN*8];   // [b][h][j][d]
__device__ __align__(16) float g_pattn[NB*NN*64];
__device__ __align__(16) float g_Kc  [NB*NN*64];     // row-major (R4-proven)
__device__ __align__(16) float g_Vc  [NB*NN*64];
__device__ __align__(16) float g_q   [NB*NLAT*64];
__device__ __align__(16) float g_q2  [NB*NLAT*64];
__device__ __align__(16) float g_Kl  [NB*NLAT*64];
__device__ __align__(16) float g_Vl  [NB*NLAT*64];

__global__ void k_nop() {}

__device__ __forceinline__ uint32_t tf32u(float x) {
    uint32_t r; asm("cvt.rna.tf32.f32 %0, %1;" : "=r"(r) : "f"(x)); return r;
}
__device__ __forceinline__ void mma8(float* d, uint32_t a0, uint32_t a1, uint32_t a2,
                                     uint32_t a3, uint32_t b0, uint32_t b1) {
    asm volatile("mma.sync.aligned.m16n8k8.row.col.f32.tf32.tf32.f32 "
        "{%0,%1,%2,%3}, {%4,%5,%6,%7}, {%8,%9}, {%0,%1,%2,%3};"
        : "+f"(d[0]), "+f"(d[1]), "+f"(d[2]), "+f"(d[3])
        : "r"(a0), "r"(a1), "r"(a2), "r"(a3), "r"(b0), "r"(b1));
}

// -------- K0: Q, K*SCALE (row-major), V (head-major). 4 rows/block --------
__global__ void k_qkv(const float* __restrict__ p, const float* __restrict__ wq,
                      const float* __restrict__ wk, const float* __restrict__ wv) {
    int blk = blockIdx.x, t = threadIdx.x;
    int r = t >> 6, col = t & 63;
    int bi = blk*4 + r;
    __shared__ float pr[4][64];
    pr[r][col] = p[bi*64 + col];
    __syncthreads();
    float aq = 0.f, ak = 0.f, av = 0.f;
#pragma unroll 8
    for (int c = 0; c < 64; c++) {
        float pv = pr[r][c];
        aq = fmaf(pv, wq[c*64 + col], aq);
        ak = fmaf(pv, wk[c*64 + col], ak);
        av = fmaf(pv, wv[c*64 + col], av);
    }
    int b = bi >> 8, j = bi & 255;
    g_Q[bi*64 + col] = aq;
    g_Kr[bi*64 + col] = ak * SC;
    g_Vt[(((b*8 + (col >> 3))*256) + j)*8 + (col & 7)] = av;
}

// -------- K1: mma.sync TF32 GEMM, LDS.128 B-fragments, on-the-fly hi/lo --------
// smem floats: e2[128*72] | Bq[32*68 uint2 = 32*136 floats] | sS[8*256]
#define E2F   (128*72)
#define BQ_O  E2F
#define SS_O  (E2F + 32*136)
#define EDGE_SMEM ((SS_O + 8*256)*4)
__global__ void __launch_bounds__(256, 3) k_edge(const float* __restrict__ e,
                                                 const float* __restrict__ we,
                                                 const float* __restrict__ mask,
                                                 const float* __restrict__ kRW) {
    extern __shared__ float sm[];
    uint2* e2 = (uint2*)sm;                 // [row][36] pairs (c, c+4)
    uint2* Bq = (uint2*)(sm + BQ_O);        // [(k*4+a)][68] n-paired
    float* sS = sm + SS_O;
    __shared__ float qrow[64];
    int tid = threadIdx.x, bi = blockIdx.x, b = bi >> 8, i = bi & 255;
    int w = tid >> 5, lane = tid & 31;
    int g = lane >> 2, a = lane & 3;

    if (tid < 64) qrow[tid] = g_Q[bi*64 + tid];
    // Bq[row=(k*4+aa)][col2=n2*16+g*2+p]: {tf32(we[ca][n*8+g]), tf32(we[ca+4][n*8+g])}, n=2*n2+p
    for (int idx = tid; idx < 2048; idx += 256) {
        int row = idx >> 6, col2 = idx & 63;
        int k = row >> 2, aa = row & 3;
        int n2 = col2 >> 4, rem = col2 & 15;
        int gg = rem >> 1, pp = rem & 1;
        int n = n2*2 + pp, ca = k*8 + aa, cc = n*8 + gg;
        uint2 v;
        v.x = tf32u(we[ca*64 + cc]);
        v.y = tf32u(we[(ca + 4)*64 + cc]);
        Bq[row*68 + col2] = v;
    }

    const float4* eg = ((const float4*)e) + (size_t)bi*4096;
    int row0 = w*16 + g;

    for (int ch = 0; ch < 2; ch++) {
        __syncthreads();
        // stage e fp32 paired: e2[r*36 + k*4 + a] = {e[r][k*8+a], e[r][k*8+a+4]}
        for (int v = tid; v < 1024; v += 256) {
            int r = v >> 3, k = v & 7;
            float4 x0 = eg[ch*2048 + r*16 + k*2];
            float4 x1 = eg[ch*2048 + r*16 + k*2 + 1];
            uint4 p0, p1;
            p0.x = __float_as_uint(x0.x); p0.y = __float_as_uint(x1.x);
            p0.z = __float_as_uint(x0.y); p0.w = __float_as_uint(x1.y);
            p1.x = __float_as_uint(x0.z); p1.y = __float_as_uint(x1.z);
            p1.z = __float_as_uint(x0.w); p1.w = __float_as_uint(x1.w);
            *(uint4*)&e2[r*36 + k*4]     = p0;
            *(uint4*)&e2[r*36 + k*4 + 2] = p1;
        }
        __syncthreads();

        float acc[8][4];
#pragma unroll
        for (int n = 0; n < 8; n++) { acc[n][0]=0.f; acc[n][1]=0.f; acc[n][2]=0.f; acc[n][3]=0.f; }
#pragma unroll
        for (int k = 0; k < 8; k++) {
            uint2 A0 = e2[row0*36 + k*4 + a];
            uint2 A1 = e2[(row0 + 8)*36 + k*4 + a];
            float x0 = __uint_as_float(A0.x), x2 = __uint_as_float(A0.y);
            float x1 = __uint_as_float(A1.x), x3 = __uint_as_float(A1.y);
            uint32_t h0 = tf32u(x0), h1 = tf32u(x1), h2 = tf32u(x2), h3 = tf32u(x3);
            uint32_t l0 = tf32u(x0 - __uint_as_float(h0));
            uint32_t l1 = tf32u(x1 - __uint_as_float(h1));
            uint32_t l2 = tf32u(x2 - __uint_as_float(h2));
            uint32_t l3 = tf32u(x3 - __uint_as_float(h3));
            const uint2* Brow = Bq + (k*4 + a)*68 + g*2;
#pragma unroll
            for (int n2 = 0; n2 < 4; n2++) {
                uint4 bb = *(const uint4*)&Brow[n2*16];
                mma8(acc[2*n2],     h0, h1, h2, h3, bb.x, bb.y);
                mma8(acc[2*n2],     l0, l1, l2, l3, bb.x, bb.y);
                mma8(acc[2*n2 + 1], h0, h1, h2, h3, bb.z, bb.w);
                mma8(acc[2*n2 + 1], l0, l1, l2, l3, bb.z, bb.w);
            }
        }

        // scores: quad-reduce acc against Q[hk]*Kr[j][hk] (validated R9/R10)
        int j0 = ch*128 + row0;
        const float2* Kr0 = (const float2*)(g_Kr + ((size_t)(b*256 + j0))*64);
        const float2* Kr1 = (const float2*)(g_Kr + ((size_t)(b*256 + j0 + 8))*64);
#pragma unroll
        for (int n = 0; n < 8; n++) {
            float2 q2 = *(const float2*)&qrow[n*8 + 2*a];
            float2 k0 = Kr0[n*4 + a];
            float2 k1 = Kr1[n*4 + a];
            float s0 = acc[n][0]*q2.x*k0.x + acc[n][1]*q2.y*k0.y;
            float s1 = acc[n][2]*q2.x*k1.x + acc[n][3]*q2.y*k1.y;
            s0 += __shfl_xor_sync(0xffffffffu, s0, 1);
            s0 += __shfl_xor_sync(0xffffffffu, s0, 2);
            s1 += __shfl_xor_sync(0xffffffffu, s1, 1);
            s1 += __shfl_xor_sync(0xffffffffu, s1, 2);
            if (a == 0) {
                sS[n*256 + j0] = s0;
                sS[n*256 + j0 + 8] = s1;
            }
        }
    }
    __syncthreads();

    // epilogue: warp = head (identical math since R7)
    int th = w, tj = lane;
    float sv[8];
#pragma unroll
    for (int jj = 0; jj < 8; jj++) sv[jj] = sS[th*256 + tj + jj*32];
    float m = sv[0];
#pragma unroll
    for (int k = 1; k < 8; k++) m = fmaxf(m, sv[k]);
#pragma unroll
    for (int off = 16; off; off >>= 1)
        m = fmaxf(m, __shfl_xor_sync(0xffffffffu, m, off));
    float mi = mask[b*256 + i];
    const float* krow = kRW + ((size_t)b*256 + i)*256;
    const float* Vb = g_Vt + ((size_t)(b*8 + th)*256)*8;
    float av[9] = {0,0,0,0,0,0,0,0,0};
#pragma unroll
    for (int k = 0; k < 8; k++) {
        int jx = tj + k*32;
        float wgt = __expf(sv[k] - m) * mi * mask[b*256 + jx] * krow[jx];
        av[0] += wgt;
        const float4* V4 = (const float4*)(Vb + jx*8);
        float4 va = V4[0], vb = V4[1];
        av[1] = fmaf(wgt, va.x, av[1]); av[2] = fmaf(wgt, va.y, av[2]);
        av[3] = fmaf(wgt, va.z, av[3]); av[4] = fmaf(wgt, va.w, av[4]);
        av[5] = fmaf(wgt, vb.x, av[5]); av[6] = fmaf(wgt, vb.y, av[6]);
        av[7] = fmaf(wgt, vb.z, av[7]); av[8] = fmaf(wgt, vb.w, av[8]);
    }
#pragma unroll
    for (int kk = 0; kk < 9; kk++)
#pragma unroll
        for (int off = 16; off; off >>= 1)
            av[kk] += __shfl_xor_sync(0xffffffffu, av[kk], off);
    if (tj == 0) {
        float inv = 1.f / fmaxf(av[0], 1e-6f);
        float4 o1 = {av[1]*inv, av[2]*inv, av[3]*inv, av[4]*inv};
        float4 o2 = {av[5]*inv, av[6]*inv, av[7]*inv, av[8]*inv};
        float4* dst = (float4*)(g_pattn + ((size_t)(b*256 + i))*64 + th*8);
        dst[0] = o1; dst[1] = o2;
    }
}

// -------- K2: h_c + tanh proj fused with Kc/Vc projection (row-major, R4) --------
__global__ void k_hckv(const float* __restrict__ hh, const float* __restrict__ p,
                       const float* __restrict__ wo, const float* __restrict__ wkv) {
    int blk = blockIdx.x, t = threadIdx.x;
    int bi0 = blk*8;
    __shared__ float pa[8][64], hcs[8][64];
    {
        int r = t >> 6, col = t & 63;
        pa[r][col]     = g_pattn[(bi0 + r)*64 + col];
        pa[r + 4][col] = g_pattn[(bi0 + r + 4)*64 + col];
    }
    __syncthreads();
    {
        int rp = t >> 6, col = t & 63;
        float a0 = 0.f, a1 = 0.f;
#pragma unroll 8
        for (int c = 0; c < 64; c++) {
            float wv = wo[c*64 + col];
            a0 = fmaf(pa[rp][c], wv, a0);
            a1 = fmaf(pa[rp + 4][c], wv, a1);
        }
        int bi = bi0 + rp;
        hcs[rp][col]     = hh[bi*64 + col] + p[bi*64 + col] + tanhf(a0);
        hcs[rp + 4][col] = hh[(bi + 4)*64 + col] + p[(bi + 4)*64 + col] + tanhf(a1);
    }
    __syncthreads();
    {
        int o = t & 127, rq = t >> 7;
        float a[4] = {0, 0, 0, 0};
#pragma unroll 8
        for (int c = 0; c < 64; c++) {
            float wv = wkv[c*128 + o];
#pragma unroll
            for (int k = 0; k < 4; k++) a[k] = fmaf(hcs[rq + 2*k][c], wv, a[k]);
        }
#pragma unroll
        for (int k = 0; k < 4; k++) {
            int bi = bi0 + rq + 2*k;
            if (o < 64) g_Kc[bi*64 + o] = a[k]; else g_Vc[bi*64 + (o - 64)] = a[k];
        }
    }
}

// -------- K3: perceiver cross-attention (row-major, R4-proven) --------
__global__ void k_cross(const float* __restrict__ queries, const float* __restrict__ mask,
                        const float* __restrict__ wq, const float* __restrict__ wo,
                        const float* __restrict__ bo) {
    int blk = blockIdx.x, b = blk >> 5, t = threadIdx.x;
    __shared__ __align__(16) float q2[64];
    __shared__ float sq[64];
    __shared__ float att[64];
    __shared__ float simb[8*256];
    if (t < 64) sq[t] = queries[blk*64 + t];
    __syncthreads();
    if (t < 64) {
        float a = 0.f;
#pragma unroll 8
        for (int c = 0; c < 64; c++) a = fmaf(sq[c], wq[c*64 + t], a);
        q2[t] = a;
    }
    __syncthreads();
    {
        int j = t;
        bool mk = mask[b*256 + j] > 0.5f;
        const float* Kr = g_Kc + ((size_t)(b*256 + j))*64;
#pragma unroll
        for (int h = 0; h < 8; h++) {
            float4 ka = *(const float4*)(Kr + h*8);
            float4 kb = *(const float4*)(Kr + h*8 + 4);
            float4 qa = *(const float4*)(q2 + h*8);
            float4 qb = *(const float4*)(q2 + h*8 + 4);
            float s = ka.x*qa.x + ka.y*qa.y + ka.z*qa.z + ka.w*qa.w
                    + kb.x*qb.x + kb.y*qb.y + kb.z*qb.z + kb.w*qb.w;
            s *= SC;
            if (!mk) s = -3.402823466e38f;
            simb[h*256 + j] = fminf(5.f, fmaxf(-5.f, s));
        }
    }
    __syncthreads();
    int h = t >> 5, lane = t & 31;
    {
        float sum = 0.f, o[8] = {0,0,0,0,0,0,0,0};
        for (int j = lane; j < 256; j += 32) {
            float ev = __expf(simb[h*256 + j]);
            sum += ev;
            const float4* V4 = (const float4*)(g_Vc + ((size_t)(b*256 + j))*64 + h*8);
            float4 va = V4[0], vb = V4[1];
            o[0] = fmaf(ev, va.x, o[0]); o[1] = fmaf(ev, va.y, o[1]);
            o[2] = fmaf(ev, va.z, o[2]); o[3] = fmaf(ev, va.w, o[3]);
            o[4] = fmaf(ev, vb.x, o[4]); o[5] = fmaf(ev, vb.y, o[5]);
            o[6] = fmaf(ev, vb.z, o[6]); o[7] = fmaf(ev, vb.w, o[7]);
        }
#pragma unroll
        for (int off = 16; off; off >>= 1) {
            sum += __shfl_xor_sync(0xffffffffu, sum, off);
#pragma unroll
            for (int d = 0; d < 8; d++) o[d] += __shfl_xor_sync(0xffffffffu, o[d], off);
        }
        if (lane == 0) {
            float inv = 1.f / sum;
#pragma unroll
            for (int d = 0; d < 8; d++) att[h*8 + d] = o[d]*inv;
        }
    }
    __syncthreads();
    if (t < 64) {
        float a = bo[t];
#pragma unroll 8
        for (int c = 0; c < 64; c++) a = fmaf(att[c], wo[c*64 + t], a);
        g_q[blk*64 + t] = sq[t] + a;
    }
}

// -------- K4a: latent self-attn projections --------
__global__ void k_selfqkv(const float* __restrict__ wq, const float* __restrict__ wkv) {
    int blk = blockIdx.x, t = threadIdx.x;
    __shared__ float qr[64];
    if (t < 64) qr[t] = g_q[blk*64 + t];
    __syncthreads();
    if (t < 64) {
        float a = 0.f;
#pragma unroll 8
        for (int c = 0; c < 64; c++) a = fmaf(qr[c], wq[c*64 + t], a);
        g_q2[blk*64 + t] = a;
    } else {
        int o = t - 64;
        float a = 0.f;
#pragma unroll 8
        for (int c = 0; c < 64; c++) a = fmaf(qr[c], wkv[c*128 + o], a);
        if (o < 64) g_Kl[blk*64 + o] = a; else g_Vl[blk*64 + (o - 64)] = a;
    }
}

// -------- K4b: latent self-attn core + proj + residual --------
__global__ void k_self(const float* __restrict__ wo, const float* __restrict__ bo) {
    int blk = blockIdx.x, b = blk >> 5, t = threadIdx.x;
    __shared__ float Ks[NLAT*64], Vs[NLAT*64], q2r[64], att[64];
    for (int idx = t; idx < NLAT*64; idx += 256) {
        Ks[idx] = g_Kl[b*NLAT*64 + idx];
        Vs[idx] = g_Vl[b*NLAT*64 + idx];
    }
    if (t < 64) q2r[t] = g_q2[blk*64 + t];
    __syncthreads();
    int h = t >> 5, j = t & 31;
    float s = 0.f;
#pragma unroll
    for (int k = 0; k < 8; k++) s = fmaf(q2r[h*8 + k], Ks[j*64 + h*8 + k], s);
    s *= SC;
    s = fminf(5.f, fmaxf(-5.f, s));
    float ev = __expf(s);
    float sum = ev;
#pragma unroll
    for (int off = 16; off; off >>= 1)
        sum += __shfl_xor_sync(0xffffffffu, sum, off);
    float o[8];
#pragma unroll
    for (int d = 0; d < 8; d++) o[d] = ev * Vs[j*64 + h*8 + d];
#pragma unroll
    for (int off = 16; off; off >>= 1)
#pragma unroll
        for (int d = 0; d < 8; d++) o[d] += __shfl_xor_sync(0xffffffffu, o[d], off);
    if (j == 0) {
        float inv = 1.f / sum;
#pragma unroll
        for (int d = 0; d < 8; d++) att[h*8 + d] = o[d]*inv;
    }
    __syncthreads();
    if (t < 64) {
        float a = bo[t];
#pragma unroll 8
        for (int c = 0; c < 64; c++) a = fmaf(att[c], wo[c*64 + t], a);
        g_q[blk*64 + t] += a;
    }
}

// -------- K5: oq_w @ + LN1 + FFN + LN2 -> out --------
__global__ void k_final(const float* __restrict__ oq, const float* __restrict__ g1,
                        const float* __restrict__ b1, const float* __restrict__ w1,
                        const float* __restrict__ w2, const float* __restrict__ g2,
                        const float* __restrict__ b2, float* __restrict__ out) {
    int blk = blockIdx.x, t = threadIdx.x;
    __shared__ float qr[64], x[64], y[64], f1[128], z[64], mv[2];
    if (t < 64) qr[t] = g_q[blk*64 + t];
    __syncthreads();
    if (t < 64) {
        float a = 0.f;
#pragma unroll 8
        for (int c = 0; c < 64; c++) a = fmaf(qr[c], oq[c*64 + t], a);
        x[t] = a;
    }
    __syncthreads();
    if (t < 32) {
        float a = x[t], bb = x[t + 32];
        float su = a + bb, sq = a*a + bb*bb;
#pragma unroll
        for (int off = 16; off; off >>= 1) {
            su += __shfl_xor_sync(0xffffffffu, su, off);
            sq += __shfl_xor_sync(0xffffffffu, sq, off);
        }
        if (t == 0) { mv[0] = su/64.f; mv[1] = sq/64.f - (su/64.f)*(su/64.f); }
    }
    __syncthreads();
    if (t < 64)
        y[t] = (x[t] - mv[0])*rsqrtf(mv[1] + 1e-5f)*g1[t] + b1[t];
    __syncthreads();
    {
        float a = 0.f;
#pragma unroll 8
        for (int c = 0; c < 64; c++) a = fmaf(y[c], w1[c*128 + t], a);
        f1[t] = fmaxf(a, 0.f);
    }
    __syncthreads();
    if (t < 64) {
        float a = 0.f;
#pragma unroll 8
        for (int c = 0; c < 128; c++) a = fmaf(f1[c], w2[c*64 + t], a);
        z[t] = y[t] + a;
    }
    __syncthreads();
    if (t < 32) {
        float a = z[t], bb = z[t + 32];
        float su = a + bb, sq = a*a + bb*bb;
#pragma unroll
        for (int off = 16; off; off >>= 1) {
            su += __shfl_xor_sync(0xffffffffu, su, off);
            sq += __shfl_xor_sync(0xffffffffu, sq, off);
        }
        if (t == 0) { mv[0] = su/64.f; mv[1] = sq/64.f - (su/64.f)*(su/64.f); }
    }
    __syncthreads();
    if (t < 64)
        out[blk*64 + t] = (z[t] - mv[0])*rsqrtf(mv[1] + 1e-5f)*g2[t] + b2[t];
}

extern "C" void kernel_launch(void* const* d_in, const int* in_sizes, int n_in,
                              void* d_out, int out_size) {
    const float* h_    = (const float*)d_in[0];
    const float* p     = (const float*)d_in[1];
    const float* e     = (const float*)d_in[2];
    const float* kRW   = (const float*)d_in[3];
    const float* qrs   = (const float*)d_in[4];
    const float* mask  = (const float*)d_in[5];
    const float* wq_p  = (const float*)d_in[6];
    const float* wk_p  = (const float*)d_in[7];
    const float* we_p  = (const float*)d_in[8];
    const float* wv_p  = (const float*)d_in[9];
    const float* wo_p  = (const float*)d_in[10];
    const float* cq_wq = (const float*)d_in[11];
    const float* cq_wkv= (const float*)d_in[12];
    const float* cq_wo = (const float*)d_in[13];
    const float* cq_bo = (const float*)d_in[14];
    const float* sa_wq = (const float*)d_in[15];
    const float* sa_wkv= (const float*)d_in[16];
    const float* sa_wo = (const float*)d_in[17];
    const float* sa_bo = (const float*)d_in[18];
    const float* oq_w  = (const float*)d_in[19];
    const float* ln1g  = (const float*)d_in[20];
    const float* ln1b  = (const float*)d_in[21];
    const float* fw1   = (const float*)d_in[22];
    const float* fw2   = (const float*)d_in[23];
    const float* ln2g  = (const float*)d_in[24];
    const float* ln2b  = (const float*)d_in[25];
    float* out = (float*)d_out;

    static int configured = 0;
    if (!configured) {
        cudaFuncSetAttribute(k_edge, cudaFuncAttributeMaxDynamicSharedMemorySize, EDGE_SMEM);
        configured = 1;
    }

    k_qkv   <<<NB*NN/4, 256>>>(p, wq_p, wk_p, wv_p);            // 1
    k_nop   <<<1, 32>>>();                                       // 2
    k_nop   <<<1, 32>>>();                                       // 3
    k_edge  <<<NB*NN, 256, EDGE_SMEM>>>(e, we_p, mask, kRW);     // 4 -> profiled
    k_hckv  <<<NB*NN/8, 256>>>(h_, p, wo_p, cq_wkv);
    k_cross <<<NB*NLAT, 256>>>(qrs, mask, cq_wq, cq_wo, cq_bo);
    for (int l = 0; l < 2; l++) {
        k_selfqkv<<<NB*NLAT, 192>>>(sa_wq + l*4096, sa_wkv + l*8192);
        k_self   <<<NB*NLAT, 256>>>(sa_wo + l*4096, sa_bo + l*64);
    }
    k_final <<<NB*NLAT, 128>>>(oq_w, ln1g, ln1b, fw1, fw2, ln2g, ln2b, out);
}